// round 4
// baseline (speedup 1.0000x reference)
#include <cuda_runtime.h>
#include <math.h>
#include <stdint.h>

// Problem constants
#define BB_ 32
#define NN_ 49
#define DD_ 512
#define MM_ (BB_*NN_)      // 1568
#define NRELV_ 14
#define EPSV_ 1e-5f
#define SCALEV_ 0.125f     // 1/sqrt(64)

// ---------------- device scratch (no allocations allowed) ----------------
__device__ __align__(256) float g_hconv[MM_*DD_];
__device__ __align__(256) float g_qr[MM_*DD_];
__device__ __align__(256) float g_eq[MM_*DD_];
__device__ __align__(256) float g_ek[MM_*DD_];
__device__ __align__(256) float g_ev[MM_*DD_];
__device__ __align__(256) float g_eqcat[MM_*1280];
__device__ __align__(256) float g_ekcat[MM_*1280];
__device__ __align__(256) float g_v[MM_*DD_];
__device__ __align__(256) float g_att[MM_*DD_];
__device__ __align__(256) float g_convWt[9*512*512];
__device__ __align__(256) float g_Bq[512*1280];
__device__ __align__(256) float g_Bk[512*1280];
__device__ __align__(256) float g_Wvr[512*512];
__device__ __align__(256) float g_Wor[512*512];
__device__ __align__(256) float g_biasq[1280];
__device__ __align__(256) float g_biask[1280];
__device__ float g_sums[1024];
__device__ float g_mu[512];
__device__ float g_is[512];
__device__ float g_wr2g[512];
__device__ float g_reg[NRELV_];
__device__ float g_c0[1];
__device__ float g_gate[MM_*NN_];

__device__ __forceinline__ float wsum(float v) {
#pragma unroll
    for (int o = 16; o > 0; o >>= 1) v += __shfl_xor_sync(0xffffffffu, v, o);
    return v;
}

__device__ __forceinline__ float to_tf32(float x) {
    uint32_t u;
    asm("cvt.rna.tf32.f32 %0, %1;" : "=r"(u) : "f"(x));
    return __uint_as_float(u);
}

__device__ __forceinline__ void mma_tf32(float* c,
                                         uint32_t a0, uint32_t a1, uint32_t a2, uint32_t a3,
                                         uint32_t b0, uint32_t b1) {
    asm volatile("mma.sync.aligned.m16n8k8.row.col.f32.tf32.tf32.f32 "
                 "{%0,%1,%2,%3}, {%4,%5,%6,%7}, {%8,%9}, {%0,%1,%2,%3};"
                 : "+f"(c[0]), "+f"(c[1]), "+f"(c[2]), "+f"(c[3])
                 : "r"(a0), "r"(a1), "r"(a2), "r"(a3), "r"(b0), "r"(b1));
}

__device__ __forceinline__ void cp16(uint32_t dst, const float* src, bool pred) {
    int sz = pred ? 16 : 0;
    asm volatile("cp.async.cg.shared.global [%0], [%1], 16, %2;\n"
                 :: "r"(dst), "l"(src), "r"(sz));
}
#define CP_COMMIT() asm volatile("cp.async.commit_group;")
#define CP_WAIT1()  asm volatile("cp.async.wait_group 1;")

// ---------------- tiny precompute: folded gate vectors ----------------
__global__ void rea_k0(const float* __restrict__ Wr2, const float* __restrict__ Wproj,
                       const float* __restrict__ Wg, const float* __restrict__ rel,
                       const float* __restrict__ br2, const float* __restrict__ bproj,
                       const float* __restrict__ bgate) {
    __shared__ float wg_s[512];
    __shared__ float wpg_s[64];
    int t = threadIdx.x;
    wg_s[t] = Wg[t];
    __syncthreads();
    float a = 0.f;
    for (int j = 0; j < 512; j++) a += Wr2[(size_t)t*512 + j] * wg_s[j];
    g_wr2g[t] = a;
    if (t < 64) {
        float s = 0.f;
        for (int j = 0; j < 512; j++) s += Wproj[(size_t)t*512 + j] * wg_s[j];
        wpg_s[t] = s;
    }
    __syncthreads();
    if (t < NRELV_) {
        float s = 0.f;
        for (int d = 0; d < 64; d++) s += rel[t*64 + d] * wpg_s[d];
        g_reg[t] = s;
    }
    if (t == 0) {
        float s = bgate[0];
        for (int j = 0; j < 512; j++) s += (br2[j] + bproj[j]) * wg_s[j];
        g_c0[0] = s;
    }
}

// ---------------- weight repacks (rounded to tf32) ----------------
__global__ void rea_repack_conv(const float* __restrict__ convW) {
    __shared__ float t[32][33];
    int tap = blockIdx.z;
    int o0 = blockIdx.x*32, c0 = blockIdx.y*32;
    int tx = threadIdx.x & 31, ty = threadIdx.x >> 5;
#pragma unroll
    for (int k = 0; k < 4; k++) {
        int o = o0 + ty + k*8;
        t[ty + k*8][tx] = to_tf32(convW[((size_t)o*512 + (c0 + tx))*9 + tap]);
    }
    __syncthreads();
#pragma unroll
    for (int k = 0; k < 4; k++) {
        int c = c0 + ty + k*8;
        g_convWt[(size_t)tap*262144 + (size_t)c*512 + o0 + tx] = t[tx][ty + k*8];
    }
}

__global__ void rea_repack_bcat(const float* __restrict__ Wq, const float* __restrict__ Wk,
                                const float* __restrict__ Wc1, const float* __restrict__ Wr1,
                                const float* __restrict__ bq, const float* __restrict__ bk) {
    int idx = blockIdx.x*blockDim.x + threadIdx.x;
    if (idx < 512*1280) {
        int k = idx / 1280, n = idx - k*1280;
        float vq, vk;
        if (n < 512)       { vq = Wq[(size_t)k*512 + n];              vk = Wk[(size_t)k*512 + n]; }
        else if (n < 768)  { vq = Wc1[(size_t)k*256 + (n-512)];       vk = Wc1[(size_t)(k+512)*256 + (n-512)]; }
        else               { vq = Wr1[(size_t)k*512 + (n-768)];       vk = Wr1[(size_t)(k+512)*512 + (n-768)]; }
        g_Bq[idx] = to_tf32(vq); g_Bk[idx] = to_tf32(vk);
    }
    if (idx < 1280) {
        g_biasq[idx] = idx < 512 ? bq[idx] : 0.f;
        g_biask[idx] = idx < 512 ? bk[idx] : 0.f;
    }
}

__global__ void rea_round_w(const float* __restrict__ Wv, const float* __restrict__ Wo) {
    int idx = blockIdx.x*blockDim.x + threadIdx.x;
    if (idx >= 512*512) return;
    g_Wvr[idx] = to_tf32(Wv[idx]);
    g_Wor[idx] = to_tf32(Wo[idx]);
}

// zero hconv/sums + round Q, one pass
__global__ void rea_prep(const float* __restrict__ Q) {
    int i = blockIdx.x*blockDim.x + threadIdx.x;
    if (i < MM_*DD_) { g_qr[i] = to_tf32(Q[i]); g_hconv[i] = 0.f; }
    if (i < 1024) g_sums[i] = 0.f;
}

// ---------------- TF32 tensor-core GEMM core ----------------
#define BMT 128
#define BNT 128
#define BKT 16
#define APAD 20
#define BPAD 136
#define SZA (BMT*APAD*4)
#define SZB (BKT*BPAD*4)

template <bool CONV, bool ATOMIC>
__device__ __forceinline__ void gemm_core(
    const float* __restrict__ A, const float* __restrict__ Bm,
    const float* __restrict__ bias, float* __restrict__ C,
    int M, int N, int lda, int kbase, int KT,
    float* AsB, float* BsB) {

    int tid = threadIdx.x;
    int lane = tid & 31, warp = tid >> 5;
    int g = lane >> 2, t4 = lane & 3;
    int wm = (warp & 1) * 64, wn = (warp >> 1) * 32;
    int m0 = blockIdx.y * BMT, n0 = blockIdx.x * BNT;

    uint32_t sA = (uint32_t)__cvta_generic_to_shared(AsB);
    uint32_t sB = (uint32_t)__cvta_generic_to_shared(BsB);

    float acc[4][4][4];
#pragma unroll
    for (int i = 0; i < 4; i++)
#pragma unroll
        for (int j = 0; j < 4; j++)
#pragma unroll
            for (int q = 0; q < 4; q++) acc[i][j][q] = 0.f;

    auto load_tile = [&](int kt, int buf) {
        int k0 = kbase + kt * BKT;
#pragma unroll
        for (int h = 0; h < 2; h++) {
            int c = tid + h*256;
            int m = c >> 2, kg = c & 3;
            int gm = m0 + m;
            int kk = k0 + kg*4;
            const float* src;
            bool pred;
            if (!CONV) {
                pred = gm < M;
                src = A + (pred ? ((size_t)gm*lda + kk) : 0);
            } else {
                int bb2 = gm / 49, pos = gm - bb2*49;
                int tap = kk >> 9, ch = kk & 511;
                int pr = pos / 7;
                int ii = pr + tap/3 - 1;
                int jj = (pos - pr*7) + (tap - (tap/3)*3) - 1;
                pred = (gm < M) & ((unsigned)ii < 7u) & ((unsigned)jj < 7u);
                size_t off = pred ? (((size_t)(bb2*49 + ii*7 + jj))*512 + ch) : 0;
                src = A + off;
            }
            cp16(sA + buf*SZA + (m*APAD + kg*4)*4, src, pred);
        }
#pragma unroll
        for (int h = 0; h < 2; h++) {
            int c = tid + h*256;
            int kr = c >> 5, ng = c & 31;
            const float* src = Bm + (size_t)(k0 + kr)*N + n0 + ng*4;
            cp16(sB + buf*SZB + (kr*BPAD + ng*4)*4, src, true);
        }
    };

    load_tile(0, 0);
    CP_COMMIT();

    for (int kt = 0; kt < KT; kt++) {
        if (kt + 1 < KT) load_tile(kt + 1, (kt + 1) & 1);
        CP_COMMIT();
        CP_WAIT1();
        __syncthreads();
        const float* as = AsB + (kt & 1)*(BMT*APAD);
        const float* bs = BsB + (kt & 1)*(BKT*BPAD);
#pragma unroll
        for (int k8 = 0; k8 < 2; k8++) {
            uint32_t af[4][4], bf[4][2];
#pragma unroll
            for (int i = 0; i < 4; i++) {
                int mrow = wm + i*16 + g;
                af[i][0] = __float_as_uint(as[mrow*APAD + k8*8 + t4]);
                af[i][1] = __float_as_uint(as[(mrow + 8)*APAD + k8*8 + t4]);
                af[i][2] = __float_as_uint(as[mrow*APAD + k8*8 + t4 + 4]);
                af[i][3] = __float_as_uint(as[(mrow + 8)*APAD + k8*8 + t4 + 4]);
            }
#pragma unroll
            for (int j = 0; j < 4; j++) {
                int nc = wn + j*8 + g;
                bf[j][0] = __float_as_uint(bs[(k8*8 + t4)*BPAD + nc]);
                bf[j][1] = __float_as_uint(bs[(k8*8 + t4 + 4)*BPAD + nc]);
            }
#pragma unroll
            for (int i = 0; i < 4; i++)
#pragma unroll
                for (int j = 0; j < 4; j++)
                    mma_tf32(acc[i][j], af[i][0], af[i][1], af[i][2], af[i][3],
                             bf[j][0], bf[j][1]);
        }
        __syncthreads();
    }

#pragma unroll
    for (int i = 0; i < 4; i++) {
        int mbase = m0 + wm + i*16 + g;
#pragma unroll
        for (int half = 0; half < 2; half++) {
            int gm = mbase + half*8;
            if (gm < M) {
#pragma unroll
                for (int j = 0; j < 4; j++) {
                    int gn = n0 + wn + j*8 + t4*2;
                    float v0 = acc[i][j][half*2 + 0];
                    float v1 = acc[i][j][half*2 + 1];
                    if (ATOMIC) {
                        if (blockIdx.z == 0 && bias) { v0 += bias[gn]; v1 += bias[gn + 1]; }
                        atomicAdd(&C[(size_t)gm*N + gn],     v0);
                        atomicAdd(&C[(size_t)gm*N + gn + 1], v1);
                    } else {
                        if (bias) { v0 += bias[gn]; v1 += bias[gn + 1]; }
                        C[(size_t)gm*N + gn]     = v0;
                        C[(size_t)gm*N + gn + 1] = v1;
                    }
                }
            }
        }
    }
}

__global__ void __launch_bounds__(256, 2)
rea_gconv(const float* __restrict__ A, const float* __restrict__ Bm,
          const float* __restrict__ bias, float* __restrict__ C) {
    __shared__ float AsB[2*BMT*APAD];
    __shared__ float BsB[2*BKT*BPAD];
    gemm_core<true, true>(A, Bm, bias, C, MM_, 512, 4608,
                          blockIdx.z*1152, 72, AsB, BsB);
}

__global__ void __launch_bounds__(256, 2)
rea_gqkv(const float* __restrict__ bv) {
    __shared__ float AsB[2*BMT*APAD];
    __shared__ float BsB[2*BKT*BPAD];
    int z = blockIdx.z;
    if (z == 2 && blockIdx.x >= 4) return;
    const float* A    = z == 0 ? g_eq    : z == 1 ? g_ek    : g_ev;
    const float* Bm   = z == 0 ? g_Bq    : z == 1 ? g_Bk    : g_Wvr;
    const float* bias = z == 0 ? g_biasq : z == 1 ? g_biask : bv;
    float*       C    = z == 0 ? g_eqcat : z == 1 ? g_ekcat : g_v;
    int N = z < 2 ? 1280 : 512;
    gemm_core<false, false>(A, Bm, bias, C, MM_, N, 512, 0, 32, AsB, BsB);
}

__global__ void __launch_bounds__(256, 2)
rea_gout(const float* __restrict__ A, const float* __restrict__ Bm,
         const float* __restrict__ bias, float* __restrict__ C) {
    __shared__ float AsB[2*BMT*APAD];
    __shared__ float BsB[2*BKT*BPAD];
    gemm_core<false, false>(A, Bm, bias, C, MM_, 512, 512, 0, 32, AsB, BsB);
}

// ---------------- batchnorm stats + finalize + eq/ek/ev ----------------
__global__ void rea_bn_stats() {
    __shared__ float ss[512], sq[512];
    int tid = threadIdx.x;
    for (int c = tid; c < 512; c += 256) { ss[c] = 0.f; sq[c] = 0.f; }
    __syncthreads();
    int r0 = blockIdx.x*32;
    for (int r = r0; r < r0 + 32; r++) {
        for (int c = tid; c < 512; c += 256) {
            float v = g_hconv[(size_t)r*512 + c];
            ss[c] += v; sq[c] += v*v;
        }
    }
    __syncthreads();
    for (int c = tid; c < 512; c += 256) {
        atomicAdd(&g_sums[c], ss[c]);
        atomicAdd(&g_sums[512 + c], sq[c]);
    }
}

__global__ void rea_bn_fin() {
    int t = threadIdx.x;
    float s = g_sums[t], q = g_sums[512 + t];
    float mu = s * (1.f/1568.f);
    float var = q * (1.f/1568.f) - mu*mu;
    g_mu[t] = mu;
    g_is[t] = rsqrtf(var + EPSV_);
}

__global__ void rea_eqkv(const float* __restrict__ Q, const float* __restrict__ Kin,
                         const float* __restrict__ Vin) {
    int idx = blockIdx.x*blockDim.x + threadIdx.x;
    if (idx >= MM_*DD_) return;
    int c = idx & 511;
    float xn = (g_hconv[idx] - g_mu[c]) * g_is[c];
    xn = fmaxf(xn, 0.f);
    g_eq[idx] = to_tf32(xn + Q[idx]);
    g_ek[idx] = to_tf32(xn + Kin[idx]);
    g_ev[idx] = to_tf32(xn + Vin[idx]);
}

// ---------------- per-pair gate kernel (smem-tiled, 7 q's x 49 k's per block) --
extern __shared__ float sm_pair[];
__global__ void __launch_bounds__(512, 1)
rea_pair(const float* __restrict__ Wc2, const float* __restrict__ bc1,
         const float* __restrict__ gc, const float* __restrict__ bcln,
         const float* __restrict__ bc2, const float* __restrict__ br1,
         const float* __restrict__ gr, const float* __restrict__ brln) {
    float* ch_k  = sm_pair;               // 49*256
    float* re_k  = ch_k + 49*256;         // 49*512
    float* pa1   = re_k + 49*512;         // 7*256
    float* par   = pa1 + 7*256;           // 7*512
    float* s_gc  = par + 7*512;           // 256
    float* s_bcl = s_gc + 256;            // 256
    float* s_gr  = s_bcl + 256;           // 512
    float* s_brl = s_gr + 512;            // 512
    float* s_w2g = s_brl + 512;           // 512
    float* s_wc2t = s_w2g + 512;          // 14*256
    float* s_bc2 = s_wc2t + 14*256;       // 16
    float* s_reg = s_bc2 + 16;            // 16

    int b = blockIdx.x, qc = blockIdx.y;
    int t = threadIdx.x;

    for (int idx = t; idx < 49*256; idx += 512) {
        int k = idx >> 8, j = idx & 255;
        ch_k[idx] = g_ekcat[(size_t)(b*49 + k)*1280 + 512 + j];
    }
    for (int idx = t; idx < 49*512; idx += 512) {
        int k = idx >> 9, j = idx & 511;
        re_k[idx] = g_ekcat[(size_t)(b*49 + k)*1280 + 768 + j];
    }
    for (int idx = t; idx < 7*256; idx += 512) {
        int q = idx >> 8, j = idx & 255;
        int m = b*49 + qc*7 + q;
        pa1[idx] = g_eqcat[(size_t)m*1280 + 512 + j] + bc1[j];
    }
    for (int idx = t; idx < 7*512; idx += 512) {
        int q = idx >> 9, j = idx & 511;
        int m = b*49 + qc*7 + q;
        par[idx] = g_eqcat[(size_t)m*1280 + 768 + j] + br1[j];
    }
    if (t < 256) { s_gc[t] = gc[t]; s_bcl[t] = bcln[t]; }
    else { int j = t - 256; s_gr[j + 256] = gr[j + 256]; }  // placeholder lane use below
    for (int j = t; j < 512; j += 512) { s_gr[j] = gr[j]; s_brl[j] = brln[j]; s_w2g[j] = g_wr2g[j]; }
    for (int idx = t; idx < 14*256; idx += 512) {
        int tt = idx >> 8, j = idx & 255;
        s_wc2t[idx] = Wc2[j*14 + tt];
    }
    if (t < NRELV_) { s_bc2[t] = bc2[t]; s_reg[t] = g_reg[t]; }
    __syncthreads();

    float c0 = g_c0[0];
    int w = t >> 5, l = t & 31;
    for (int p = w; p < 343; p += 16) {
        int q = p / 49, k = p - q*49;
        const float* chk = ch_k + k*256;
        const float* rek = re_k + k*512;
        const float* pq1 = pa1 + q*256;
        const float* pqr = par + q*512;
        // ---- channel branch: LN(256) -> relu -> @Wc2 -> softmax(14) dot reg --
        float xc[8]; float s = 0.f;
#pragma unroll
        for (int jj = 0; jj < 8; jj++) { int j = l + 32*jj; xc[jj] = pq1[j] + chk[j]; s += xc[jj]; }
        s = wsum(s);
        float mean = s * (1.f/256.f);
        float vs = 0.f;
#pragma unroll
        for (int jj = 0; jj < 8; jj++) { float d = xc[jj] - mean; vs += d*d; }
        vs = wsum(vs);
        float rs = rsqrtf(vs*(1.f/256.f) + EPSV_);
        float lg[14];
#pragma unroll
        for (int tt = 0; tt < 14; tt++) lg[tt] = 0.f;
#pragma unroll
        for (int jj = 0; jj < 8; jj++) {
            int j = l + 32*jj;
            float y = (xc[jj] - mean)*rs*s_gc[j] + s_bcl[j];
            y = fmaxf(y, 0.f);
#pragma unroll
            for (int tt = 0; tt < 14; tt++) lg[tt] += y * s_wc2t[tt*256 + j];
        }
#pragma unroll
        for (int o = 16; o > 0; o >>= 1) {
#pragma unroll
            for (int tt = 0; tt < 14; tt++) lg[tt] += __shfl_xor_sync(0xffffffffu, lg[tt], o);
        }
        float mx = -1e30f;
#pragma unroll
        for (int tt = 0; tt < 14; tt++) { lg[tt] += s_bc2[tt]; mx = fmaxf(mx, lg[tt]); }
        float se = 0.f, dg = 0.f;
#pragma unroll
        for (int tt = 0; tt < 14; tt++) { float e = expf(lg[tt] - mx); se += e; dg += e*s_reg[tt]; }
        float proj = dg / se * (1.f/(1.f + 1e-8f));
        // ---- relation branch: LN(512) -> relu -> dot(wr2g) ----
        float xr[16]; float sr = 0.f;
#pragma unroll
        for (int jj = 0; jj < 16; jj++) { int j = l + 32*jj; xr[jj] = pqr[j] + rek[j]; sr += xr[jj]; }
        sr = wsum(sr);
        float mr = sr * (1.f/512.f);
        float vr = 0.f;
#pragma unroll
        for (int jj = 0; jj < 16; jj++) { float d = xr[jj] - mr; vr += d*d; }
        vr = wsum(vr);
        float rsr = rsqrtf(vr*(1.f/512.f) + EPSV_);
        float dr = 0.f;
#pragma unroll
        for (int jj = 0; jj < 16; jj++) {
            int j = l + 32*jj;
            float y = (xr[jj] - mr)*rsr*s_gr[j] + s_brl[j];
            y = fmaxf(y, 0.f);
            dr += y * s_w2g[j];
        }
        dr = wsum(dr);
        if (l == 0) {
            float ga = dr + proj + c0;
            g_gate[(size_t)(b*49 + qc*7 + q)*49 + k] = 1.f/(1.f + expf(-ga));
        }
    }
}
#define PAIR_SMEM ((49*256 + 49*512 + 7*256 + 7*512 + 256 + 256 + 512 + 512 + 512 + 14*256 + 16 + 16)*4)

// ---------------- attention per (b,h): smem tiles, no per-k shuffles ----------
__global__ void __launch_bounds__(256)
rea_attn(float* __restrict__ out) {
    __shared__ float Qt[49*65], Kt[49*65], Vt[49*65];
    __shared__ float wrow[8][52];
    int h = blockIdx.x, b = blockIdx.y;
    int t = threadIdx.x, w = t >> 5, l = t & 31;

    for (int idx = t; idx < 49*64; idx += 256) {
        int q = idx >> 6, d = idx & 63;
        Qt[q*65 + d] = g_eqcat[(size_t)(b*49 + q)*1280 + h*64 + d];
        Kt[q*65 + d] = g_ekcat[(size_t)(b*49 + q)*1280 + h*64 + d];
        Vt[q*65 + d] = g_v[(size_t)(b*49 + q)*512 + h*64 + d];
    }
    __syncthreads();

    for (int q = w; q < 49; q += 8) {
        int m = b*49 + q;
        int k2 = l + 32;
        bool v2 = k2 < 49;
        float g1 = g_gate[(size_t)m*49 + l];
        float g2 = v2 ? g_gate[(size_t)m*49 + k2] : 0.f;
        const float* qr  = Qt + q*65;
        const float* k1r = Kt + l*65;
        const float* k2r = Kt + (v2 ? k2 : l)*65;
        float d1 = 0.f, d2 = 0.f;
#pragma unroll 8
        for (int d = 0; d < 64; d++) {
            float qv = qr[d];
            d1 += qv * k1r[d];
            d2 += qv * k2r[d];
        }
        float lv1 = d1*SCALEV_*(1.f + g1);
        float lv2 = v2 ? d2*SCALEV_*(1.f + g2) : -1e30f;
        float mx = fmaxf(lv1, lv2);
#pragma unroll
        for (int o = 16; o > 0; o >>= 1) mx = fmaxf(mx, __shfl_xor_sync(0xffffffffu, mx, o));
        float e1 = expf(lv1 - mx);
        float e2 = v2 ? expf(lv2 - mx) : 0.f;
        float ssum = wsum(e1 + e2);
        float inv = 1.f / ssum;
        wrow[w][l] = e1 * inv;
        if (v2) wrow[w][k2] = e2 * inv;
        __syncwarp();
        float a1 = 0.f, a2 = 0.f;
        for (int k = 0; k < 49; k++) {
            float wk = wrow[w][k];
            a1 += wk * Vt[k*65 + l];
            a2 += wk * Vt[k*65 + l + 32];
        }
        out[(size_t)m*512 + h*64 + l]      = to_tf32(a1);
        out[(size_t)m*512 + h*64 + l + 32] = to_tf32(a2);
        __syncwarp();
    }
}

// ---------------- launch ----------------
extern "C" void kernel_launch(void* const* d_in, const int* in_sizes, int n_in,
                              void* d_out, int out_size) {
    const float* Q     = (const float*)d_in[0];
    const float* Kin   = (const float*)d_in[1];
    const float* Vin   = (const float*)d_in[2];
    const float* Wq    = (const float*)d_in[3];
    const float* bq    = (const float*)d_in[4];
    const float* Wk    = (const float*)d_in[5];
    const float* bk    = (const float*)d_in[6];
    const float* Wv    = (const float*)d_in[7];
    const float* bv    = (const float*)d_in[8];
    const float* Wo    = (const float*)d_in[9];
    const float* bo    = (const float*)d_in[10];
    const float* rel   = (const float*)d_in[11];
    const float* Wproj = (const float*)d_in[12];
    const float* bproj = (const float*)d_in[13];
    const float* Wgate = (const float*)d_in[14];
    const float* bgate = (const float*)d_in[15];
    const float* Wc1   = (const float*)d_in[16];
    const float* bc1   = (const float*)d_in[17];
    const float* gc    = (const float*)d_in[18];
    const float* bcln  = (const float*)d_in[19];
    const float* Wc2   = (const float*)d_in[20];
    const float* bc2   = (const float*)d_in[21];
    const float* Wr1   = (const float*)d_in[22];
    const float* br1   = (const float*)d_in[23];
    const float* gr    = (const float*)d_in[24];
    const float* brln  = (const float*)d_in[25];
    const float* Wr2   = (const float*)d_in[26];
    const float* br2   = (const float*)d_in[27];
    const float* convW = (const float*)d_in[28];
    const float* convb = (const float*)d_in[29];

    void *p_hconv, *p_qr, *p_att, *p_convWt, *p_Wor;
    cudaGetSymbolAddress(&p_hconv, g_hconv);
    cudaGetSymbolAddress(&p_qr, g_qr);
    cudaGetSymbolAddress(&p_att, g_att);
    cudaGetSymbolAddress(&p_convWt, g_convWt);
    cudaGetSymbolAddress(&p_Wor, g_Wor);

    cudaFuncSetAttribute(rea_pair, cudaFuncAttributeMaxDynamicSharedMemorySize, PAIR_SMEM);

    // Order chosen so rea_gconv is the 4th launch (ncu captures launch idx 3).
    rea_repack_conv<<<dim3(16, 16, 9), 256>>>(convW);
    rea_prep<<<(MM_*DD_ + 255)/256, 256>>>(Q);
    rea_k0<<<1, 512>>>(Wr2, Wproj, Wgate, rel, br2, bproj, bgate);
    rea_gconv<<<dim3(4, 13, 4), 256>>>((const float*)p_qr, (const float*)p_convWt,
                                       convb, (float*)p_hconv);

    rea_repack_bcat<<<(512*1280 + 255)/256, 256>>>(Wq, Wk, Wc1, Wr1, bq, bk);
    rea_round_w<<<(512*512 + 255)/256, 256>>>(Wv, Wo);
    rea_bn_stats<<<49, 256>>>();
    rea_bn_fin<<<1, 512>>>();
    rea_eqkv<<<(MM_*DD_ + 255)/256, 256>>>(Q, Kin, Vin);

    rea_gqkv<<<dim3(10, 13, 3), 256>>>(bv);

    rea_pair<<<dim3(32, 7), 512, PAIR_SMEM>>>(Wc2, bc1, gc, bcln, bc2, br1, gr, brln);
    rea_attn<<<dim3(8, 32), 256>>>((float*)p_att);

    rea_gout<<<dim3(4, 13), 256>>>((const float*)p_att, (const float*)p_Wor,
                                   bo, (float*)d_out);
}

// round 5
// speedup vs baseline: 1.4253x; 1.4253x over previous
#include <cuda_runtime.h>
#include <math.h>
#include <stdint.h>

// Problem constants
#define BB_ 32
#define NN_ 49
#define DD_ 512
#define MM_ (BB_*NN_)      // 1568
#define NRELV_ 14
#define EPSV_ 1e-5f
#define SCALEV_ 0.125f     // 1/sqrt(64)

// ---------------- device scratch (no allocations allowed) ----------------
__device__ __align__(256) float g_hconv[MM_*DD_];
__device__ __align__(256) float g_qr[MM_*DD_];
__device__ __align__(256) float g_eq[MM_*DD_];
__device__ __align__(256) float g_ek[MM_*DD_];
__device__ __align__(256) float g_ev[MM_*DD_];
__device__ __align__(256) float g_eqcat[MM_*1280];
__device__ __align__(256) float g_ekcat[MM_*1280];
__device__ __align__(256) float g_v[MM_*DD_];
__device__ __align__(256) float g_att[MM_*DD_];
__device__ __align__(256) float g_convWt[9*512*512];
__device__ __align__(256) float g_Bq[512*1280];
__device__ __align__(256) float g_Bk[512*1280];
__device__ __align__(256) float g_Wvr[512*512];
__device__ __align__(256) float g_Wor[512*512];
__device__ __align__(256) float g_biasq[1280];
__device__ __align__(256) float g_biask[1280];
__device__ float g_sums[1024];
__device__ float g_wr2g[512];
__device__ float g_reg[NRELV_];
__device__ float g_c0[1];
__device__ float g_gate[MM_*NN_];

__device__ __forceinline__ float wsum(float v) {
#pragma unroll
    for (int o = 16; o > 0; o >>= 1) v += __shfl_xor_sync(0xffffffffu, v, o);
    return v;
}

__device__ __forceinline__ float to_tf32(float x) {
    uint32_t u;
    asm("cvt.rna.tf32.f32 %0, %1;" : "=r"(u) : "f"(x));
    return __uint_as_float(u);
}

__device__ __forceinline__ void mma_tf32(float* c,
                                         uint32_t a0, uint32_t a1, uint32_t a2, uint32_t a3,
                                         uint32_t b0, uint32_t b1) {
    asm volatile("mma.sync.aligned.m16n8k8.row.col.f32.tf32.tf32.f32 "
                 "{%0,%1,%2,%3}, {%4,%5,%6,%7}, {%8,%9}, {%0,%1,%2,%3};"
                 : "+f"(c[0]), "+f"(c[1]), "+f"(c[2]), "+f"(c[3])
                 : "r"(a0), "r"(a1), "r"(a2), "r"(a3), "r"(b0), "r"(b1));
}

__device__ __forceinline__ void cp16(uint32_t dst, const float* src, bool pred) {
    int sz = pred ? 16 : 0;
    asm volatile("cp.async.cg.shared.global [%0], [%1], 16, %2;\n"
                 :: "r"(dst), "l"(src), "r"(sz));
}
#define CP_COMMIT() asm volatile("cp.async.commit_group;")
#define CP_WAIT1()  asm volatile("cp.async.wait_group 1;")

// ---------------- folded gate vectors: parallel version ----------------
// grid 65 x 256 threads. blocks 0..63: wr2g rows; block 64: wpg/reg/c0.
__global__ void rea_k0(const float* __restrict__ Wr2, const float* __restrict__ Wproj,
                       const float* __restrict__ Wg, const float* __restrict__ rel,
                       const float* __restrict__ br2, const float* __restrict__ bproj,
                       const float* __restrict__ bgate) {
    __shared__ float wg_s[512];
    __shared__ float wpg_s[64];
    int t = threadIdx.x;
    wg_s[t] = Wg[t];
    wg_s[t + 256] = Wg[t + 256];
    __syncthreads();
    int w = t >> 5, l = t & 31;
    if (blockIdx.x < 64) {
        int row = blockIdx.x*8 + w;
        float s = 0.f;
        for (int j = l; j < 512; j += 32) s += Wr2[(size_t)row*512 + j] * wg_s[j];
        s = wsum(s);
        if (l == 0) g_wr2g[row] = s;
    } else {
        for (int r = w; r < 64; r += 8) {
            float s = 0.f;
            for (int j = l; j < 512; j += 32) s += Wproj[(size_t)r*512 + j] * wg_s[j];
            s = wsum(s);
            if (l == 0) wpg_s[r] = s;
        }
        __syncthreads();
        if (t < NRELV_) {
            float s = 0.f;
            for (int d = 0; d < 64; d++) s += rel[t*64 + d] * wpg_s[d];
            g_reg[t] = s;
        }
        if (w == 7) {
            float s = 0.f;
            for (int j = l; j < 512; j += 32) s += (br2[j] + bproj[j]) * wg_s[j];
            s = wsum(s);
            if (l == 0) g_c0[0] = s + bgate[0];
        }
    }
}

// ---------------- weight repacks (rounded to tf32) ----------------
__global__ void rea_repack_conv(const float* __restrict__ convW) {
    __shared__ float t[32][33];
    int tap = blockIdx.z;
    int o0 = blockIdx.x*32, c0 = blockIdx.y*32;
    int tx = threadIdx.x & 31, ty = threadIdx.x >> 5;
#pragma unroll
    for (int k = 0; k < 4; k++) {
        int o = o0 + ty + k*8;
        t[ty + k*8][tx] = to_tf32(convW[((size_t)o*512 + (c0 + tx))*9 + tap]);
    }
    __syncthreads();
#pragma unroll
    for (int k = 0; k < 4; k++) {
        int c = c0 + ty + k*8;
        g_convWt[(size_t)tap*262144 + (size_t)c*512 + o0 + tx] = t[tx][ty + k*8];
    }
}

__global__ void rea_repack_bcat(const float* __restrict__ Wq, const float* __restrict__ Wk,
                                const float* __restrict__ Wc1, const float* __restrict__ Wr1,
                                const float* __restrict__ bq, const float* __restrict__ bk,
                                const float* __restrict__ Wv, const float* __restrict__ Wo) {
    int idx = blockIdx.x*blockDim.x + threadIdx.x;
    if (idx < 512*1280) {
        int k = idx / 1280, n = idx - k*1280;
        float vq, vk;
        if (n < 512)       { vq = Wq[(size_t)k*512 + n];              vk = Wk[(size_t)k*512 + n]; }
        else if (n < 768)  { vq = Wc1[(size_t)k*256 + (n-512)];       vk = Wc1[(size_t)(k+512)*256 + (n-512)]; }
        else               { vq = Wr1[(size_t)k*512 + (n-768)];       vk = Wr1[(size_t)(k+512)*512 + (n-768)]; }
        g_Bq[idx] = to_tf32(vq); g_Bk[idx] = to_tf32(vk);
    }
    if (idx < 512*512) {
        g_Wvr[idx] = to_tf32(Wv[idx]);
        g_Wor[idx] = to_tf32(Wo[idx]);
    }
    if (idx < 1280) {
        g_biasq[idx] = idx < 512 ? bq[idx] : 0.f;
        g_biask[idx] = idx < 512 ? bk[idx] : 0.f;
    }
}

// zero hconv/sums + round Q, one pass
__global__ void rea_prep(const float* __restrict__ Q) {
    int i = blockIdx.x*blockDim.x + threadIdx.x;
    if (i < MM_*DD_) { g_qr[i] = to_tf32(Q[i]); g_hconv[i] = 0.f; }
    if (i < 1024) g_sums[i] = 0.f;
}

// ---------------- TF32 tensor-core GEMM core ----------------
#define BMT 128
#define BNT 128
#define BKT 16
#define APAD 20
#define BPAD 136
#define SZA (BMT*APAD*4)
#define SZB (BKT*BPAD*4)

template <bool CONV, bool ATOMIC>
__device__ __forceinline__ void gemm_core(
    const float* __restrict__ A, const float* __restrict__ Bm,
    const float* __restrict__ bias, float* __restrict__ C,
    int M, int N, int lda, int kbase, int KT,
    float* AsB, float* BsB) {

    int tid = threadIdx.x;
    int lane = tid & 31, warp = tid >> 5;
    int g = lane >> 2, t4 = lane & 3;
    int wm = (warp & 1) * 64, wn = (warp >> 1) * 32;
    int m0 = blockIdx.y * BMT, n0 = blockIdx.x * BNT;

    uint32_t sA = (uint32_t)__cvta_generic_to_shared(AsB);
    uint32_t sB = (uint32_t)__cvta_generic_to_shared(BsB);

    float acc[4][4][4];
#pragma unroll
    for (int i = 0; i < 4; i++)
#pragma unroll
        for (int j = 0; j < 4; j++)
#pragma unroll
            for (int q = 0; q < 4; q++) acc[i][j][q] = 0.f;

    auto load_tile = [&](int kt, int buf) {
        int k0 = kbase + kt * BKT;
#pragma unroll
        for (int h = 0; h < 2; h++) {
            int c = tid + h*256;
            int m = c >> 2, kg = c & 3;
            int gm = m0 + m;
            int kk = k0 + kg*4;
            const float* src;
            bool pred;
            if (!CONV) {
                pred = gm < M;
                src = A + (pred ? ((size_t)gm*lda + kk) : 0);
            } else {
                int bb2 = gm / 49, pos = gm - bb2*49;
                int tap = kk >> 9, ch = kk & 511;
                int pr = pos / 7;
                int ii = pr + tap/3 - 1;
                int jj = (pos - pr*7) + (tap - (tap/3)*3) - 1;
                pred = (gm < M) & ((unsigned)ii < 7u) & ((unsigned)jj < 7u);
                size_t off = pred ? (((size_t)(bb2*49 + ii*7 + jj))*512 + ch) : 0;
                src = A + off;
            }
            cp16(sA + buf*SZA + (m*APAD + kg*4)*4, src, pred);
        }
#pragma unroll
        for (int h = 0; h < 2; h++) {
            int c = tid + h*256;
            int kr = c >> 5, ng = c & 31;
            const float* src = Bm + (size_t)(k0 + kr)*N + n0 + ng*4;
            cp16(sB + buf*SZB + (kr*BPAD + ng*4)*4, src, true);
        }
    };

    load_tile(0, 0);
    CP_COMMIT();

    for (int kt = 0; kt < KT; kt++) {
        if (kt + 1 < KT) load_tile(kt + 1, (kt + 1) & 1);
        CP_COMMIT();
        CP_WAIT1();
        __syncthreads();
        const float* as = AsB + (kt & 1)*(BMT*APAD);
        const float* bs = BsB + (kt & 1)*(BKT*BPAD);
#pragma unroll
        for (int k8 = 0; k8 < 2; k8++) {
            uint32_t af[4][4], bf[4][2];
#pragma unroll
            for (int i = 0; i < 4; i++) {
                int mrow = wm + i*16 + g;
                af[i][0] = __float_as_uint(as[mrow*APAD + k8*8 + t4]);
                af[i][1] = __float_as_uint(as[(mrow + 8)*APAD + k8*8 + t4]);
                af[i][2] = __float_as_uint(as[mrow*APAD + k8*8 + t4 + 4]);
                af[i][3] = __float_as_uint(as[(mrow + 8)*APAD + k8*8 + t4 + 4]);
            }
#pragma unroll
            for (int j = 0; j < 4; j++) {
                int nc = wn + j*8 + g;
                bf[j][0] = __float_as_uint(bs[(k8*8 + t4)*BPAD + nc]);
                bf[j][1] = __float_as_uint(bs[(k8*8 + t4 + 4)*BPAD + nc]);
            }
#pragma unroll
            for (int i = 0; i < 4; i++)
#pragma unroll
                for (int j = 0; j < 4; j++)
                    mma_tf32(acc[i][j], af[i][0], af[i][1], af[i][2], af[i][3],
                             bf[j][0], bf[j][1]);
        }
        __syncthreads();
    }

#pragma unroll
    for (int i = 0; i < 4; i++) {
        int mbase = m0 + wm + i*16 + g;
#pragma unroll
        for (int half = 0; half < 2; half++) {
            int gm = mbase + half*8;
            if (gm < M) {
#pragma unroll
                for (int j = 0; j < 4; j++) {
                    int gn = n0 + wn + j*8 + t4*2;
                    float v0 = acc[i][j][half*2 + 0];
                    float v1 = acc[i][j][half*2 + 1];
                    if (ATOMIC) {
                        if (blockIdx.z == 0 && bias) { v0 += bias[gn]; v1 += bias[gn + 1]; }
                        atomicAdd(&C[(size_t)gm*N + gn],     v0);
                        atomicAdd(&C[(size_t)gm*N + gn + 1], v1);
                    } else {
                        if (bias) { v0 += bias[gn]; v1 += bias[gn + 1]; }
                        C[(size_t)gm*N + gn]     = v0;
                        C[(size_t)gm*N + gn + 1] = v1;
                    }
                }
            }
        }
    }
}

__global__ void __launch_bounds__(256, 2)
rea_gconv(const float* __restrict__ A, const float* __restrict__ Bm,
          const float* __restrict__ bias, float* __restrict__ C) {
    __shared__ float AsB[2*BMT*APAD];
    __shared__ float BsB[2*BKT*BPAD];
    gemm_core<true, true>(A, Bm, bias, C, MM_, 512, 4608,
                          blockIdx.z*1152, 72, AsB, BsB);
}

__global__ void __launch_bounds__(256, 2)
rea_gqkv(const float* __restrict__ bv) {
    __shared__ float AsB[2*BMT*APAD];
    __shared__ float BsB[2*BKT*BPAD];
    int z = blockIdx.z;
    if (z == 2 && blockIdx.x >= 4) return;
    const float* A    = z == 0 ? g_eq    : z == 1 ? g_ek    : g_ev;
    const float* Bm   = z == 0 ? g_Bq    : z == 1 ? g_Bk    : g_Wvr;
    const float* bias = z == 0 ? g_biasq : z == 1 ? g_biask : bv;
    float*       C    = z == 0 ? g_eqcat : z == 1 ? g_ekcat : g_v;
    int N = z < 2 ? 1280 : 512;
    gemm_core<false, false>(A, Bm, bias, C, MM_, N, 512, 0, 32, AsB, BsB);
}

__global__ void __launch_bounds__(256, 2)
rea_gout(const float* __restrict__ A, const float* __restrict__ Bm,
         const float* __restrict__ bias, float* __restrict__ C) {
    __shared__ float AsB[2*BMT*APAD];
    __shared__ float BsB[2*BKT*BPAD];
    gemm_core<false, false>(A, Bm, bias, C, MM_, 512, 512, 0, 32, AsB, BsB);
}

// ---------------- batchnorm stats + eq/ek/ev (bn finalize inlined) ----------
__global__ void rea_bn_stats() {
    __shared__ float ss[512], sq[512];
    int tid = threadIdx.x;
    for (int c = tid; c < 512; c += 256) { ss[c] = 0.f; sq[c] = 0.f; }
    __syncthreads();
    int r0 = blockIdx.x*32;
    for (int r = r0; r < r0 + 32; r++) {
        for (int c = tid; c < 512; c += 256) {
            float v = g_hconv[(size_t)r*512 + c];
            ss[c] += v; sq[c] += v*v;
        }
    }
    __syncthreads();
    for (int c = tid; c < 512; c += 256) {
        atomicAdd(&g_sums[c], ss[c]);
        atomicAdd(&g_sums[512 + c], sq[c]);
    }
}

__global__ void rea_eqkv(const float* __restrict__ Q, const float* __restrict__ Kin,
                         const float* __restrict__ Vin) {
    int idx = blockIdx.x*blockDim.x + threadIdx.x;
    if (idx >= MM_*DD_) return;
    int c = idx & 511;
    float mu = g_sums[c] * (1.f/1568.f);
    float var = g_sums[512 + c] * (1.f/1568.f) - mu*mu;
    float isd = rsqrtf(var + EPSV_);
    float xn = (g_hconv[idx] - mu) * isd;
    xn = fmaxf(xn, 0.f);
    g_eq[idx] = to_tf32(xn + Q[idx]);
    g_ek[idx] = to_tf32(xn + Kin[idx]);
    g_ev[idx] = to_tf32(xn + Vin[idx]);
}

// ---------------- per-pair gate: one pair per LANE, j-dim tiled in smem ------
// grid (32, 5), 512 threads. Block handles pairs [by*512, by*512+512) of the
// 2401 pairs of batch b. Lane-private LN stats + 14 logit accumulators:
// zero cross-lane communication in the hot loops.
#define PTILE 64
__global__ void __launch_bounds__(512)
rea_pair(const float* __restrict__ Wc2, const float* __restrict__ bc1,
         const float* __restrict__ gc, const float* __restrict__ bcln,
         const float* __restrict__ bc2, const float* __restrict__ br1,
         const float* __restrict__ gr, const float* __restrict__ brln) {
    __shared__ float ck_s[PTILE*49];
    __shared__ float pq_s[PTILE*49];
    __shared__ float wct_s[PTILE*16];
    __shared__ float2 ab_s[PTILE];
    __shared__ float w2_s[PTILE];
    __shared__ float s_bc2[16], s_reg[16];

    int b = blockIdx.x;
    int t = threadIdx.x;
    int p = blockIdx.y*512 + t;
    int q = p / 49, k = p - q*49;
    bool act = q < 49;
    int qc = act ? q : 48;
    int b49 = b*49;

    if (t < NRELV_) { s_bc2[t] = bc2[t]; s_reg[t] = g_reg[t]; }
    if (t < PTILE) { wct_s[t*16 + 14] = 0.f; wct_s[t*16 + 15] = 0.f; }

    // ======== channel branch (256 dims, eqcat/ekcat offset 512) ========
    float s1 = 0.f, s2 = 0.f;
    for (int jt = 0; jt < 4; jt++) {
        int j0 = jt*PTILE;
        __syncthreads();
        for (int idx = t; idx < PTILE*49; idx += 512) {
            int kk = idx >> 6, j = idx & 63;
            size_t base = (size_t)(b49 + kk)*1280 + 512 + j0 + j;
            ck_s[j*49 + kk] = g_ekcat[base];
            pq_s[j*49 + kk] = g_eqcat[base] + bc1[j0 + j];
        }
        __syncthreads();
#pragma unroll 8
        for (int j = 0; j < PTILE; j++) {
            float xc = pq_s[j*49 + qc] + ck_s[j*49 + k];
            s1 += xc; s2 = fmaf(xc, xc, s2);
        }
    }
    float mu = s1 * (1.f/256.f);
    float rs = rsqrtf(s2*(1.f/256.f) - mu*mu + EPSV_);

    float lg[14];
#pragma unroll
    for (int i = 0; i < 14; i++) lg[i] = 0.f;
    for (int jt = 0; jt < 4; jt++) {
        int j0 = jt*PTILE;
        __syncthreads();
        for (int idx = t; idx < PTILE*49; idx += 512) {
            int kk = idx >> 6, j = idx & 63;
            size_t base = (size_t)(b49 + kk)*1280 + 512 + j0 + j;
            ck_s[j*49 + kk] = g_ekcat[base];
            pq_s[j*49 + kk] = g_eqcat[base] + bc1[j0 + j];
        }
        for (int idx = t; idx < PTILE*14; idx += 512) {
            int j = idx / 14, tt = idx - j*14;
            wct_s[j*16 + tt] = Wc2[(size_t)(j0 + j)*14 + tt];
        }
        if (t < PTILE) ab_s[t] = make_float2(gc[j0 + t], bcln[j0 + t]);
        __syncthreads();
#pragma unroll 4
        for (int j = 0; j < PTILE; j++) {
            float xc = pq_s[j*49 + qc] + ck_s[j*49 + k];
            float2 ab = ab_s[j];
            float A = rs * ab.x;
            float y = fmaxf(fmaf(xc, A, ab.y - mu*A), 0.f);
            const float4* w4 = (const float4*)&wct_s[j*16];
            float4 w0 = w4[0], w1 = w4[1], w2v = w4[2], w3v = w4[3];
            lg[0]  = fmaf(y, w0.x,  lg[0]);  lg[1]  = fmaf(y, w0.y,  lg[1]);
            lg[2]  = fmaf(y, w0.z,  lg[2]);  lg[3]  = fmaf(y, w0.w,  lg[3]);
            lg[4]  = fmaf(y, w1.x,  lg[4]);  lg[5]  = fmaf(y, w1.y,  lg[5]);
            lg[6]  = fmaf(y, w1.z,  lg[6]);  lg[7]  = fmaf(y, w1.w,  lg[7]);
            lg[8]  = fmaf(y, w2v.x, lg[8]);  lg[9]  = fmaf(y, w2v.y, lg[9]);
            lg[10] = fmaf(y, w2v.z, lg[10]); lg[11] = fmaf(y, w2v.w, lg[11]);
            lg[12] = fmaf(y, w3v.x, lg[12]); lg[13] = fmaf(y, w3v.y, lg[13]);
        }
    }
    // lane-local softmax(14) dot reg
    float mx = -1e30f;
#pragma unroll
    for (int tt = 0; tt < 14; tt++) { lg[tt] += s_bc2[tt]; mx = fmaxf(mx, lg[tt]); }
    float se = 0.f, dg = 0.f;
#pragma unroll
    for (int tt = 0; tt < 14; tt++) { float e = expf(lg[tt] - mx); se += e; dg += e*s_reg[tt]; }
    float proj = dg / se * (1.f/(1.f + 1e-8f));

    // ======== relation branch (512 dims, offset 768) ========
    s1 = 0.f; s2 = 0.f;
    for (int jt = 0; jt < 8; jt++) {
        int j0 = jt*PTILE;
        __syncthreads();
        for (int idx = t; idx < PTILE*49; idx += 512) {
            int kk = idx >> 6, j = idx & 63;
            size_t base = (size_t)(b49 + kk)*1280 + 768 + j0 + j;
            ck_s[j*49 + kk] = g_ekcat[base];
            pq_s[j*49 + kk] = g_eqcat[base] + br1[j0 + j];
        }
        __syncthreads();
#pragma unroll 8
        for (int j = 0; j < PTILE; j++) {
            float xr = pq_s[j*49 + qc] + ck_s[j*49 + k];
            s1 += xr; s2 = fmaf(xr, xr, s2);
        }
    }
    float mur = s1 * (1.f/512.f);
    float rsr = rsqrtf(s2*(1.f/512.f) - mur*mur + EPSV_);

    float dr = 0.f;
    for (int jt = 0; jt < 8; jt++) {
        int j0 = jt*PTILE;
        __syncthreads();
        for (int idx = t; idx < PTILE*49; idx += 512) {
            int kk = idx >> 6, j = idx & 63;
            size_t base = (size_t)(b49 + kk)*1280 + 768 + j0 + j;
            ck_s[j*49 + kk] = g_ekcat[base];
            pq_s[j*49 + kk] = g_eqcat[base] + br1[j0 + j];
        }
        if (t < PTILE) {
            ab_s[t] = make_float2(gr[j0 + t], brln[j0 + t]);
            w2_s[t] = g_wr2g[j0 + t];
        }
        __syncthreads();
#pragma unroll 8
        for (int j = 0; j < PTILE; j++) {
            float xr = pq_s[j*49 + qc] + ck_s[j*49 + k];
            float2 ab = ab_s[j];
            float A = rsr * ab.x;
            float y = fmaxf(fmaf(xr, A, ab.y - mur*A), 0.f);
            dr = fmaf(y, w2_s[j], dr);
        }
    }

    if (act) {
        float ga = dr + proj + g_c0[0];
        g_gate[(size_t)(b49 + q)*49 + k] = 1.f/(1.f + expf(-ga));
    }
}

// ---------------- attention per (b,h): smem tiles, no per-k shuffles ----------
__global__ void __launch_bounds__(256)
rea_attn(float* __restrict__ out) {
    __shared__ float Qt[49*65], Kt[49*65], Vt[49*65];
    __shared__ float wrow[8][52];
    int h = blockIdx.x, b = blockIdx.y;
    int t = threadIdx.x, w = t >> 5, l = t & 31;

    for (int idx = t; idx < 49*64; idx += 256) {
        int q = idx >> 6, d = idx & 63;
        Qt[q*65 + d] = g_eqcat[(size_t)(b*49 + q)*1280 + h*64 + d];
        Kt[q*65 + d] = g_ekcat[(size_t)(b*49 + q)*1280 + h*64 + d];
        Vt[q*65 + d] = g_v[(size_t)(b*49 + q)*512 + h*64 + d];
    }
    __syncthreads();

    for (int q = w; q < 49; q += 8) {
        int m = b*49 + q;
        int k2 = l + 32;
        bool v2 = k2 < 49;
        float g1 = g_gate[(size_t)m*49 + l];
        float g2 = v2 ? g_gate[(size_t)m*49 + k2] : 0.f;
        const float* qr  = Qt + q*65;
        const float* k1r = Kt + l*65;
        const float* k2r = Kt + (v2 ? k2 : l)*65;
        float d1 = 0.f, d2 = 0.f;
#pragma unroll 8
        for (int d = 0; d < 64; d++) {
            float qv = qr[d];
            d1 += qv * k1r[d];
            d2 += qv * k2r[d];
        }
        float lv1 = d1*SCALEV_*(1.f + g1);
        float lv2 = v2 ? d2*SCALEV_*(1.f + g2) : -1e30f;
        float mx = fmaxf(lv1, lv2);
#pragma unroll
        for (int o = 16; o > 0; o >>= 1) mx = fmaxf(mx, __shfl_xor_sync(0xffffffffu, mx, o));
        float e1 = expf(lv1 - mx);
        float e2 = v2 ? expf(lv2 - mx) : 0.f;
        float ssum = wsum(e1 + e2);
        float inv = 1.f / ssum;
        wrow[w][l] = e1 * inv;
        if (v2) wrow[w][k2] = e2 * inv;
        __syncwarp();
        float a1 = 0.f, a2 = 0.f;
        for (int k = 0; k < 49; k++) {
            float wk = wrow[w][k];
            a1 += wk * Vt[k*65 + l];
            a2 += wk * Vt[k*65 + l + 32];
        }
        out[(size_t)m*512 + h*64 + l]      = to_tf32(a1);
        out[(size_t)m*512 + h*64 + l + 32] = to_tf32(a2);
        __syncwarp();
    }
}

// ---------------- launch ----------------
extern "C" void kernel_launch(void* const* d_in, const int* in_sizes, int n_in,
                              void* d_out, int out_size) {
    const float* Q     = (const float*)d_in[0];
    const float* Kin   = (const float*)d_in[1];
    const float* Vin   = (const float*)d_in[2];
    const float* Wq    = (const float*)d_in[3];
    const float* bq    = (const float*)d_in[4];
    const float* Wk    = (const float*)d_in[5];
    const float* bk    = (const float*)d_in[6];
    const float* Wv    = (const float*)d_in[7];
    const float* bv    = (const float*)d_in[8];
    const float* Wo    = (const float*)d_in[9];
    const float* bo    = (const float*)d_in[10];
    const float* rel   = (const float*)d_in[11];
    const float* Wproj = (const float*)d_in[12];
    const float* bproj = (const float*)d_in[13];
    const float* Wgate = (const float*)d_in[14];
    const float* bgate = (const float*)d_in[15];
    const float* Wc1   = (const float*)d_in[16];
    const float* bc1   = (const float*)d_in[17];
    const float* gc    = (const float*)d_in[18];
    const float* bcln  = (const float*)d_in[19];
    const float* Wc2   = (const float*)d_in[20];
    const float* bc2   = (const float*)d_in[21];
    const float* Wr1   = (const float*)d_in[22];
    const float* br1   = (const float*)d_in[23];
    const float* gr    = (const float*)d_in[24];
    const float* brln  = (const float*)d_in[25];
    const float* Wr2   = (const float*)d_in[26];
    const float* br2   = (const float*)d_in[27];
    const float* convW = (const float*)d_in[28];
    const float* convb = (const float*)d_in[29];

    void *p_hconv, *p_qr, *p_att, *p_convWt, *p_Wor;
    cudaGetSymbolAddress(&p_hconv, g_hconv);
    cudaGetSymbolAddress(&p_qr, g_qr);
    cudaGetSymbolAddress(&p_att, g_att);
    cudaGetSymbolAddress(&p_convWt, g_convWt);
    cudaGetSymbolAddress(&p_Wor, g_Wor);

    // gconv stays 4th launch (ncu captures launch idx 3)
    rea_repack_conv<<<dim3(16, 16, 9), 256>>>(convW);
    rea_prep<<<(MM_*DD_ + 255)/256, 256>>>(Q);
    rea_k0<<<65, 256>>>(Wr2, Wproj, Wgate, rel, br2, bproj, bgate);
    rea_gconv<<<dim3(4, 13, 4), 256>>>((const float*)p_qr, (const float*)p_convWt,
                                       convb, (float*)p_hconv);

    rea_repack_bcat<<<(512*1280 + 255)/256, 256>>>(Wq, Wk, Wc1, Wr1, bq, bk, Wv, Wo);
    rea_bn_stats<<<49, 256>>>();
    rea_eqkv<<<(MM_*DD_ + 255)/256, 256>>>(Q, Kin, Vin);

    rea_gqkv<<<dim3(10, 13, 3), 256>>>(bv);

    rea_pair<<<dim3(32, 5), 512>>>(Wc2, bc1, gc, bcln, bc2, br1, gr, brln);
    rea_attn<<<dim3(8, 32), 256>>>((float*)p_att);

    rea_gout<<<dim3(4, 13), 256>>>((const float*)p_att, (const float*)p_Wor,
                                   bo, (float*)d_out);
}

// round 6
// speedup vs baseline: 1.5219x; 1.0677x over previous
#include <cuda_runtime.h>
#include <math.h>
#include <stdint.h>

// Problem constants
#define BB_ 32
#define NN_ 49
#define DD_ 512
#define MM_ (BB_*NN_)      // 1568
#define NRELV_ 14
#define EPSV_ 1e-5f
#define SCALEV_ 0.125f     // 1/sqrt(64)

// ---------------- device scratch (no allocations allowed) ----------------
__device__ __align__(256) float g_hconv[MM_*DD_];
__device__ __align__(256) float g_qr[MM_*DD_];
__device__ __align__(256) float g_eq[MM_*DD_];
__device__ __align__(256) float g_ek[MM_*DD_];
__device__ __align__(256) float g_ev[MM_*DD_];
__device__ __align__(256) float g_eqcat[MM_*1280];
__device__ __align__(256) float g_ekcat[MM_*1280];
__device__ __align__(256) float g_v[MM_*DD_];
__device__ __align__(256) float g_att[MM_*DD_];
__device__ __align__(256) float g_convWt[9*512*512];
__device__ __align__(256) float g_Bq[512*1280];
__device__ __align__(256) float g_Bk[512*1280];
__device__ __align__(256) float g_Wvr[512*512];
__device__ __align__(256) float g_Wor[512*512];
__device__ __align__(256) float g_biasq[1280];
__device__ __align__(256) float g_biask[1280];
__device__ float g_sums[1024];
__device__ float g_wr2g[512];
__device__ float g_reg[NRELV_];
__device__ float g_c0[1];
__device__ float g_gate[MM_*NN_];

__device__ __forceinline__ float wsum(float v) {
#pragma unroll
    for (int o = 16; o > 0; o >>= 1) v += __shfl_xor_sync(0xffffffffu, v, o);
    return v;
}

__device__ __forceinline__ float to_tf32(float x) {
    uint32_t u;
    asm("cvt.rna.tf32.f32 %0, %1;" : "=r"(u) : "f"(x));
    return __uint_as_float(u);
}

__device__ __forceinline__ void mma_tf32(float* c,
                                         uint32_t a0, uint32_t a1, uint32_t a2, uint32_t a3,
                                         uint32_t b0, uint32_t b1) {
    asm volatile("mma.sync.aligned.m16n8k8.row.col.f32.tf32.tf32.f32 "
                 "{%0,%1,%2,%3}, {%4,%5,%6,%7}, {%8,%9}, {%0,%1,%2,%3};"
                 : "+f"(c[0]), "+f"(c[1]), "+f"(c[2]), "+f"(c[3])
                 : "r"(a0), "r"(a1), "r"(a2), "r"(a3), "r"(b0), "r"(b1));
}

__device__ __forceinline__ void cp16(uint32_t dst, const float* src, bool pred) {
    int sz = pred ? 16 : 0;
    asm volatile("cp.async.cg.shared.global [%0], [%1], 16, %2;\n"
                 :: "r"(dst), "l"(src), "r"(sz));
}
#define CP_COMMIT() asm volatile("cp.async.commit_group;" ::: "memory")
#define CP_WAIT1()  asm volatile("cp.async.wait_group 1;" ::: "memory")

// ---------------- folded gate vectors: parallel version ----------------
__global__ void rea_k0(const float* __restrict__ Wr2, const float* __restrict__ Wproj,
                       const float* __restrict__ Wg, const float* __restrict__ rel,
                       const float* __restrict__ br2, const float* __restrict__ bproj,
                       const float* __restrict__ bgate) {
    __shared__ float wg_s[512];
    __shared__ float wpg_s[64];
    int t = threadIdx.x;
    wg_s[t] = Wg[t];
    wg_s[t + 256] = Wg[t + 256];
    __syncthreads();
    int w = t >> 5, l = t & 31;
    if (blockIdx.x < 64) {
        int row = blockIdx.x*8 + w;
        float s = 0.f;
        for (int j = l; j < 512; j += 32) s += Wr2[(size_t)row*512 + j] * wg_s[j];
        s = wsum(s);
        if (l == 0) g_wr2g[row] = s;
    } else {
        for (int r = w; r < 64; r += 8) {
            float s = 0.f;
            for (int j = l; j < 512; j += 32) s += Wproj[(size_t)r*512 + j] * wg_s[j];
            s = wsum(s);
            if (l == 0) wpg_s[r] = s;
        }
        __syncthreads();
        if (t < NRELV_) {
            float s = 0.f;
            for (int d = 0; d < 64; d++) s += rel[t*64 + d] * wpg_s[d];
            g_reg[t] = s;
        }
        if (w == 7) {
            float s = 0.f;
            for (int j = l; j < 512; j += 32) s += (br2[j] + bproj[j]) * wg_s[j];
            s = wsum(s);
            if (l == 0) g_c0[0] = s + bgate[0];
        }
    }
}

// ---------------- conv weight repack, fully coalesced both sides ----------
// convW [O=512][C=512][T=9] -> g_convWt [T][C][O]. Block: 32 o x 32 c x 9 t.
__global__ void rea_repack_conv(const float* __restrict__ convW) {
    __shared__ float ts[32*289];
    int o0 = blockIdx.x*32, c0 = blockIdx.y*32;
    int t = threadIdx.x;
    for (int idx = t; idx < 32*288; idx += 256) {
        int o = idx / 288, r = idx - o*288;   // r = c_local*9 + tap
        ts[o*289 + r] = to_tf32(convW[((size_t)(o0 + o)*512 + c0)*9 + r]);
    }
    __syncthreads();
    for (int idx = t; idx < 288*32; idx += 256) {
        int row = idx >> 5, o = idx & 31;
        int c = row / 9, tap = row - c*9;
        g_convWt[(size_t)tap*262144 + (size_t)(c0 + c)*512 + o0 + o] = ts[o*289 + row];
    }
}

__global__ void rea_repack_bcat(const float* __restrict__ Wq, const float* __restrict__ Wk,
                                const float* __restrict__ Wc1, const float* __restrict__ Wr1,
                                const float* __restrict__ bq, const float* __restrict__ bk,
                                const float* __restrict__ Wv, const float* __restrict__ Wo) {
    int idx = blockIdx.x*blockDim.x + threadIdx.x;
    if (idx < 512*1280) {
        int k = idx / 1280, n = idx - k*1280;
        float vq, vk;
        if (n < 512)       { vq = Wq[(size_t)k*512 + n];              vk = Wk[(size_t)k*512 + n]; }
        else if (n < 768)  { vq = Wc1[(size_t)k*256 + (n-512)];       vk = Wc1[(size_t)(k+512)*256 + (n-512)]; }
        else               { vq = Wr1[(size_t)k*512 + (n-768)];       vk = Wr1[(size_t)(k+512)*512 + (n-768)]; }
        g_Bq[idx] = to_tf32(vq); g_Bk[idx] = to_tf32(vk);
    }
    if (idx < 512*512) {
        g_Wvr[idx] = to_tf32(Wv[idx]);
        g_Wor[idx] = to_tf32(Wo[idx]);
    }
    if (idx < 1280) {
        g_biasq[idx] = idx < 512 ? bq[idx] : 0.f;
        g_biask[idx] = idx < 512 ? bk[idx] : 0.f;
    }
}

// zero hconv/sums + round Q, one pass
__global__ void rea_prep(const float* __restrict__ Q) {
    int i = blockIdx.x*blockDim.x + threadIdx.x;
    if (i < MM_*DD_) { g_qr[i] = to_tf32(Q[i]); g_hconv[i] = 0.f; }
    if (i < 1024) g_sums[i] = 0.f;
}

// ---------------- TF32 tensor-core GEMM core (3-stage cp.async ring) --------
#define BMT 128
#define BNT 128
#define BKT 16
#define APAD 20
#define BPAD 136
#define SZA (BMT*APAD*4)
#define SZB (BKT*BPAD*4)
#define GEMM_SMEM (3*(BMT*APAD + BKT*BPAD)*4)

template <bool CONV, bool ATOMIC>
__device__ __forceinline__ void gemm_core(
    const float* __restrict__ A, const float* __restrict__ Bm,
    const float* __restrict__ bias, float* __restrict__ C,
    int M, int N, int lda, int kbase, int KT, int di, int dj,
    float* AsB, float* BsB) {

    int tid = threadIdx.x;
    int lane = tid & 31, warp = tid >> 5;
    int g = lane >> 2, t4 = lane & 3;
    int wm = (warp & 1) * 64, wn = (warp >> 1) * 32;
    int m0 = blockIdx.y * BMT, n0 = blockIdx.x * BNT;

    uint32_t sA = (uint32_t)__cvta_generic_to_shared(AsB);
    uint32_t sB = (uint32_t)__cvta_generic_to_shared(BsB);

    float acc[4][4][4];
#pragma unroll
    for (int i = 0; i < 4; i++)
#pragma unroll
        for (int j = 0; j < 4; j++)
#pragma unroll
            for (int q = 0; q < 4; q++) acc[i][j][q] = 0.f;

    // hoisted per-thread load slots (2 A + 2 B chunks of 16B)
    const float* aptr[2]; bool apred[2]; uint32_t adst[2];
    const float* bptr[2]; uint32_t bdst[2];
#pragma unroll
    for (int h = 0; h < 2; h++) {
        int c = tid + h*256;
        int m = c >> 2, kg = c & 3;
        int gm = m0 + m;
        bool pred;
        const float* p;
        if (!CONV) {
            pred = gm < M;
            p = A + (size_t)(pred ? gm : 0)*lda + kbase + kg*4;
        } else {
            int bb = gm / 49, pos = gm - bb*49;
            int pr = pos / 7, pc = pos - pr*7;
            int ii = pr + di, jj = pc + dj;
            pred = (gm < M) & ((unsigned)ii < 7u) & ((unsigned)jj < 7u);
            p = pred ? (A + ((size_t)(bb*49 + ii*7 + jj))*512 + kg*4) : A;
        }
        apred[h] = pred; aptr[h] = p;
        adst[h] = sA + (uint32_t)(m*APAD + kg*4)*4;
        int kr = c >> 5, ng = c & 31;
        bptr[h] = Bm + (size_t)(kbase + kr)*N + n0 + ng*4;
        bdst[h] = sB + (uint32_t)(kr*BPAD + ng*4)*4;
    }

    auto load_tile = [&](int kt, int buf) {
#pragma unroll
        for (int h = 0; h < 2; h++)
            cp16(adst[h] + buf*SZA, aptr[h] + kt*BKT, apred[h]);
#pragma unroll
        for (int h = 0; h < 2; h++)
            cp16(bdst[h] + buf*SZB, bptr[h] + (size_t)kt*BKT*N, true);
    };

    load_tile(0, 0); CP_COMMIT();
    if (KT > 1) load_tile(1, 1);
    CP_COMMIT();

    int buf = 0, nbuf = 2;
    for (int kt = 0; kt < KT; kt++) {
        CP_WAIT1();
        __syncthreads();
        if (kt + 2 < KT) load_tile(kt + 2, nbuf);
        CP_COMMIT();
        const float* as = AsB + buf*(BMT*APAD);
        const float* bs = BsB + buf*(BKT*BPAD);
#pragma unroll
        for (int k8 = 0; k8 < 2; k8++) {
            uint32_t af[4][4], bf[4][2];
#pragma unroll
            for (int i = 0; i < 4; i++) {
                int mrow = wm + i*16 + g;
                af[i][0] = __float_as_uint(as[mrow*APAD + k8*8 + t4]);
                af[i][1] = __float_as_uint(as[(mrow + 8)*APAD + k8*8 + t4]);
                af[i][2] = __float_as_uint(as[mrow*APAD + k8*8 + t4 + 4]);
                af[i][3] = __float_as_uint(as[(mrow + 8)*APAD + k8*8 + t4 + 4]);
            }
#pragma unroll
            for (int j = 0; j < 4; j++) {
                int nc = wn + j*8 + g;
                bf[j][0] = __float_as_uint(bs[(k8*8 + t4)*BPAD + nc]);
                bf[j][1] = __float_as_uint(bs[(k8*8 + t4 + 4)*BPAD + nc]);
            }
#pragma unroll
            for (int i = 0; i < 4; i++)
#pragma unroll
                for (int j = 0; j < 4; j++)
                    mma_tf32(acc[i][j], af[i][0], af[i][1], af[i][2], af[i][3],
                             bf[j][0], bf[j][1]);
        }
        buf = (buf == 2) ? 0 : buf + 1;
        nbuf = (nbuf == 2) ? 0 : nbuf + 1;
    }

#pragma unroll
    for (int i = 0; i < 4; i++) {
        int mbase = m0 + wm + i*16 + g;
#pragma unroll
        for (int half = 0; half < 2; half++) {
            int gm = mbase + half*8;
            if (gm < M) {
#pragma unroll
                for (int j = 0; j < 4; j++) {
                    int gn = n0 + wn + j*8 + t4*2;
                    float v0 = acc[i][j][half*2 + 0];
                    float v1 = acc[i][j][half*2 + 1];
                    if (ATOMIC) {
                        if (blockIdx.z == 0 && bias) { v0 += bias[gn]; v1 += bias[gn + 1]; }
                        atomicAdd(&C[(size_t)gm*N + gn],     v0);
                        atomicAdd(&C[(size_t)gm*N + gn + 1], v1);
                    } else {
                        if (bias) { v0 += bias[gn]; v1 += bias[gn + 1]; }
                        C[(size_t)gm*N + gn]     = v0;
                        C[(size_t)gm*N + gn + 1] = v1;
                    }
                }
            }
        }
    }
}

extern __shared__ float sm_gemm[];

// conv as implicit GEMM, split-K=9 (one tap per z), atomic accumulate
__global__ void __launch_bounds__(256, 2)
rea_gconv(const float* __restrict__ A, const float* __restrict__ Bm,
          const float* __restrict__ bias, float* __restrict__ C) {
    int tap = blockIdx.z;
    gemm_core<true, true>(A, Bm, bias, C, MM_, 512, 512,
                          tap*512, 32, tap/3 - 1, tap%3 - 1,
                          sm_gemm, sm_gemm + 3*BMT*APAD);
}

__global__ void __launch_bounds__(256, 2)
rea_gqkv(const float* __restrict__ bv) {
    int z = blockIdx.z;
    if (z == 2 && blockIdx.x >= 4) return;
    const float* A    = z == 0 ? g_eq    : z == 1 ? g_ek    : g_ev;
    const float* Bm   = z == 0 ? g_Bq    : z == 1 ? g_Bk    : g_Wvr;
    const float* bias = z == 0 ? g_biasq : z == 1 ? g_biask : bv;
    float*       C    = z == 0 ? g_eqcat : z == 1 ? g_ekcat : g_v;
    int N = z < 2 ? 1280 : 512;
    gemm_core<false, false>(A, Bm, bias, C, MM_, N, 512, 0, 32, 0, 0,
                            sm_gemm, sm_gemm + 3*BMT*APAD);
}

// output projection, split-K=4, atomic into pre-zeroed d_out
__global__ void __launch_bounds__(256, 2)
rea_gout(const float* __restrict__ A, const float* __restrict__ Bm,
         const float* __restrict__ bias, float* __restrict__ C) {
    gemm_core<false, true>(A, Bm, bias, C, MM_, 512, 512,
                           blockIdx.z*128, 8, 0, 0,
                           sm_gemm, sm_gemm + 3*BMT*APAD);
}

// ---------------- batchnorm stats + eq/ek/ev (bn finalize inlined) ----------
__global__ void rea_bn_stats() {
    __shared__ float ss[512], sq[512];
    int tid = threadIdx.x;
    for (int c = tid; c < 512; c += 256) { ss[c] = 0.f; sq[c] = 0.f; }
    __syncthreads();
    int r0 = blockIdx.x*32;
    for (int r = r0; r < r0 + 32; r++) {
        for (int c = tid; c < 512; c += 256) {
            float v = g_hconv[(size_t)r*512 + c];
            ss[c] += v; sq[c] += v*v;
        }
    }
    __syncthreads();
    for (int c = tid; c < 512; c += 256) {
        atomicAdd(&g_sums[c], ss[c]);
        atomicAdd(&g_sums[512 + c], sq[c]);
    }
}

__global__ void rea_eqkv(const float* __restrict__ Q, const float* __restrict__ Kin,
                         const float* __restrict__ Vin) {
    int idx = blockIdx.x*blockDim.x + threadIdx.x;
    if (idx >= MM_*DD_) return;
    int c = idx & 511;
    float mu = g_sums[c] * (1.f/1568.f);
    float var = g_sums[512 + c] * (1.f/1568.f) - mu*mu;
    float isd = rsqrtf(var + EPSV_);
    float xn = (g_hconv[idx] - mu) * isd;
    xn = fmaxf(xn, 0.f);
    g_eq[idx] = to_tf32(xn + Q[idx]);
    g_ek[idx] = to_tf32(xn + Kin[idx]);
    g_ev[idx] = to_tf32(xn + Vin[idx]);
}

// ---------------- per-pair gate: one pair per LANE, j-dim tiled in smem ------
#define PTILE 64
__global__ void __launch_bounds__(512)
rea_pair(const float* __restrict__ Wc2, const float* __restrict__ bc1,
         const float* __restrict__ gc, const float* __restrict__ bcln,
         const float* __restrict__ bc2, const float* __restrict__ br1,
         const float* __restrict__ gr, const float* __restrict__ brln) {
    __shared__ float ck_s[PTILE*49];
    __shared__ float pq_s[PTILE*49];
    __shared__ float wct_s[PTILE*16];
    __shared__ float2 ab_s[PTILE];
    __shared__ float w2_s[PTILE];
    __shared__ float s_bc2[16], s_reg[16];

    int b = blockIdx.x;
    int t = threadIdx.x;
    int p = blockIdx.y*512 + t;
    int q = p / 49, k = p - q*49;
    bool act = q < 49;
    int qc = act ? q : 48;
    int b49 = b*49;

    if (t < NRELV_) { s_bc2[t] = bc2[t]; s_reg[t] = g_reg[t]; }
    if (t < PTILE) { wct_s[t*16 + 14] = 0.f; wct_s[t*16 + 15] = 0.f; }

    // ======== channel branch (256 dims, offset 512) ========
    float s1 = 0.f, s2 = 0.f;
    for (int jt = 0; jt < 4; jt++) {
        int j0 = jt*PTILE;
        __syncthreads();
        for (int idx = t; idx < PTILE*49; idx += 512) {
            int kk = idx >> 6, j = idx & 63;
            size_t base = (size_t)(b49 + kk)*1280 + 512 + j0 + j;
            ck_s[j*49 + kk] = g_ekcat[base];
            pq_s[j*49 + kk] = g_eqcat[base] + bc1[j0 + j];
        }
        __syncthreads();
#pragma unroll 8
        for (int j = 0; j < PTILE; j++) {
            float xc = pq_s[j*49 + qc] + ck_s[j*49 + k];
            s1 += xc; s2 = fmaf(xc, xc, s2);
        }
    }
    float mu = s1 * (1.f/256.f);
    float rs = rsqrtf(s2*(1.f/256.f) - mu*mu + EPSV_);

    float lg[14];
#pragma unroll
    for (int i = 0; i < 14; i++) lg[i] = 0.f;
    for (int jt = 0; jt < 4; jt++) {
        int j0 = jt*PTILE;
        __syncthreads();
        for (int idx = t; idx < PTILE*49; idx += 512) {
            int kk = idx >> 6, j = idx & 63;
            size_t base = (size_t)(b49 + kk)*1280 + 512 + j0 + j;
            ck_s[j*49 + kk] = g_ekcat[base];
            pq_s[j*49 + kk] = g_eqcat[base] + bc1[j0 + j];
        }
        for (int idx = t; idx < PTILE*14; idx += 512) {
            int j = idx / 14, tt = idx - j*14;
            wct_s[j*16 + tt] = Wc2[(size_t)(j0 + j)*14 + tt];
        }
        if (t < PTILE) ab_s[t] = make_float2(gc[j0 + t], bcln[j0 + t]);
        __syncthreads();
#pragma unroll 4
        for (int j = 0; j < PTILE; j++) {
            float xc = pq_s[j*49 + qc] + ck_s[j*49 + k];
            float2 ab = ab_s[j];
            float A = rs * ab.x;
            float y = fmaxf(fmaf(xc, A, ab.y - mu*A), 0.f);
            const float4* w4 = (const float4*)&wct_s[j*16];
            float4 w0 = w4[0], w1 = w4[1], w2v = w4[2], w3v = w4[3];
            lg[0]  = fmaf(y, w0.x,  lg[0]);  lg[1]  = fmaf(y, w0.y,  lg[1]);
            lg[2]  = fmaf(y, w0.z,  lg[2]);  lg[3]  = fmaf(y, w0.w,  lg[3]);
            lg[4]  = fmaf(y, w1.x,  lg[4]);  lg[5]  = fmaf(y, w1.y,  lg[5]);
            lg[6]  = fmaf(y, w1.z,  lg[6]);  lg[7]  = fmaf(y, w1.w,  lg[7]);
            lg[8]  = fmaf(y, w2v.x, lg[8]);  lg[9]  = fmaf(y, w2v.y, lg[9]);
            lg[10] = fmaf(y, w2v.z, lg[10]); lg[11] = fmaf(y, w2v.w, lg[11]);
            lg[12] = fmaf(y, w3v.x, lg[12]); lg[13] = fmaf(y, w3v.y, lg[13]);
        }
    }
    float mx = -1e30f;
#pragma unroll
    for (int tt = 0; tt < 14; tt++) { lg[tt] += s_bc2[tt]; mx = fmaxf(mx, lg[tt]); }
    float se = 0.f, dg = 0.f;
#pragma unroll
    for (int tt = 0; tt < 14; tt++) { float e = expf(lg[tt] - mx); se += e; dg += e*s_reg[tt]; }
    float proj = dg / se * (1.f/(1.f + 1e-8f));

    // ======== relation branch (512 dims, offset 768) ========
    s1 = 0.f; s2 = 0.f;
    for (int jt = 0; jt < 8; jt++) {
        int j0 = jt*PTILE;
        __syncthreads();
        for (int idx = t; idx < PTILE*49; idx += 512) {
            int kk = idx >> 6, j = idx & 63;
            size_t base = (size_t)(b49 + kk)*1280 + 768 + j0 + j;
            ck_s[j*49 + kk] = g_ekcat[base];
            pq_s[j*49 + kk] = g_eqcat[base] + br1[j0 + j];
        }
        __syncthreads();
#pragma unroll 8
        for (int j = 0; j < PTILE; j++) {
            float xr = pq_s[j*49 + qc] + ck_s[j*49 + k];
            s1 += xr; s2 = fmaf(xr, xr, s2);
        }
    }
    float mur = s1 * (1.f/512.f);
    float rsr = rsqrtf(s2*(1.f/512.f) - mur*mur + EPSV_);

    float dr = 0.f;
    for (int jt = 0; jt < 8; jt++) {
        int j0 = jt*PTILE;
        __syncthreads();
        for (int idx = t; idx < PTILE*49; idx += 512) {
            int kk = idx >> 6, j = idx & 63;
            size_t base = (size_t)(b49 + kk)*1280 + 768 + j0 + j;
            ck_s[j*49 + kk] = g_ekcat[base];
            pq_s[j*49 + kk] = g_eqcat[base] + br1[j0 + j];
        }
        if (t < PTILE) {
            ab_s[t] = make_float2(gr[j0 + t], brln[j0 + t]);
            w2_s[t] = g_wr2g[j0 + t];
        }
        __syncthreads();
#pragma unroll 8
        for (int j = 0; j < PTILE; j++) {
            float xr = pq_s[j*49 + qc] + ck_s[j*49 + k];
            float2 ab = ab_s[j];
            float A = rsr * ab.x;
            float y = fmaxf(fmaf(xr, A, ab.y - mur*A), 0.f);
            dr = fmaf(y, w2_s[j], dr);
        }
    }

    if (act) {
        float ga = dr + proj + g_c0[0];
        g_gate[(size_t)(b49 + q)*49 + k] = 1.f/(1.f + expf(-ga));
    }
}

// ---------------- attention per (b,h); also zeroes d_out for atomic gout ----
__global__ void __launch_bounds__(256)
rea_attn(float* __restrict__ out, float* __restrict__ dz) {
    __shared__ float Qt[49*65], Kt[49*65], Vt[49*65];
    __shared__ float wrow[8][52];
    int h = blockIdx.x, b = blockIdx.y;
    int t = threadIdx.x, w = t >> 5, l = t & 31;

    // zero a 784-float4 slice of d_out (256 blocks x 784 = 802816 floats)
    {
        float4 z4 = make_float4(0.f, 0.f, 0.f, 0.f);
        float4* dst = (float4*)dz + (size_t)(b*8 + h)*784;
        for (int i = t; i < 784; i += 256) dst[i] = z4;
    }

    for (int idx = t; idx < 49*64; idx += 256) {
        int q = idx >> 6, d = idx & 63;
        Qt[q*65 + d] = g_eqcat[(size_t)(b*49 + q)*1280 + h*64 + d];
        Kt[q*65 + d] = g_ekcat[(size_t)(b*49 + q)*1280 + h*64 + d];
        Vt[q*65 + d] = g_v[(size_t)(b*49 + q)*512 + h*64 + d];
    }
    __syncthreads();

    for (int q = w; q < 49; q += 8) {
        int m = b*49 + q;
        int k2 = l + 32;
        bool v2 = k2 < 49;
        float g1 = g_gate[(size_t)m*49 + l];
        float g2 = v2 ? g_gate[(size_t)m*49 + k2] : 0.f;
        const float* qr  = Qt + q*65;
        const float* k1r = Kt + l*65;
        const float* k2r = Kt + (v2 ? k2 : l)*65;
        float d1 = 0.f, d2 = 0.f;
#pragma unroll 8
        for (int d = 0; d < 64; d++) {
            float qv = qr[d];
            d1 += qv * k1r[d];
            d2 += qv * k2r[d];
        }
        float lv1 = d1*SCALEV_*(1.f + g1);
        float lv2 = v2 ? d2*SCALEV_*(1.f + g2) : -1e30f;
        float mx = fmaxf(lv1, lv2);
#pragma unroll
        for (int o = 16; o > 0; o >>= 1) mx = fmaxf(mx, __shfl_xor_sync(0xffffffffu, mx, o));
        float e1 = expf(lv1 - mx);
        float e2 = v2 ? expf(lv2 - mx) : 0.f;
        float ssum = wsum(e1 + e2);
        float inv = 1.f / ssum;
        wrow[w][l] = e1 * inv;
        if (v2) wrow[w][k2] = e2 * inv;
        __syncwarp();
        float a1 = 0.f, a2 = 0.f;
        for (int k = 0; k < 49; k++) {
            float wk = wrow[w][k];
            a1 += wk * Vt[k*65 + l];
            a2 += wk * Vt[k*65 + l + 32];
        }
        out[(size_t)m*512 + h*64 + l]      = to_tf32(a1);
        out[(size_t)m*512 + h*64 + l + 32] = to_tf32(a2);
        __syncwarp();
    }
}

// ---------------- launch ----------------
extern "C" void kernel_launch(void* const* d_in, const int* in_sizes, int n_in,
                              void* d_out, int out_size) {
    const float* Q     = (const float*)d_in[0];
    const float* Kin   = (const float*)d_in[1];
    const float* Vin   = (const float*)d_in[2];
    const float* Wq    = (const float*)d_in[3];
    const float* bq    = (const float*)d_in[4];
    const float* Wk    = (const float*)d_in[5];
    const float* bk    = (const float*)d_in[6];
    const float* Wv    = (const float*)d_in[7];
    const float* bv    = (const float*)d_in[8];
    const float* Wo    = (const float*)d_in[9];
    const float* bo    = (const float*)d_in[10];
    const float* rel   = (const float*)d_in[11];
    const float* Wproj = (const float*)d_in[12];
    const float* bproj = (const float*)d_in[13];
    const float* Wgate = (const float*)d_in[14];
    const float* bgate = (const float*)d_in[15];
    const float* Wc1   = (const float*)d_in[16];
    const float* bc1   = (const float*)d_in[17];
    const float* gc    = (const float*)d_in[18];
    const float* bcln  = (const float*)d_in[19];
    const float* Wc2   = (const float*)d_in[20];
    const float* bc2   = (const float*)d_in[21];
    const float* Wr1   = (const float*)d_in[22];
    const float* br1   = (const float*)d_in[23];
    const float* gr    = (const float*)d_in[24];
    const float* brln  = (const float*)d_in[25];
    const float* Wr2   = (const float*)d_in[26];
    const float* br2   = (const float*)d_in[27];
    const float* convW = (const float*)d_in[28];
    const float* convb = (const float*)d_in[29];

    void *p_hconv, *p_qr, *p_att, *p_convWt, *p_Wor;
    cudaGetSymbolAddress(&p_hconv, g_hconv);
    cudaGetSymbolAddress(&p_qr, g_qr);
    cudaGetSymbolAddress(&p_att, g_att);
    cudaGetSymbolAddress(&p_convWt, g_convWt);
    cudaGetSymbolAddress(&p_Wor, g_Wor);

    static bool attr_set = false;
    if (!attr_set) {
        cudaFuncSetAttribute(rea_gconv, cudaFuncAttributeMaxDynamicSharedMemorySize, GEMM_SMEM);
        cudaFuncSetAttribute(rea_gqkv, cudaFuncAttributeMaxDynamicSharedMemorySize, GEMM_SMEM);
        cudaFuncSetAttribute(rea_gout, cudaFuncAttributeMaxDynamicSharedMemorySize, GEMM_SMEM);
        attr_set = true;
    }

    // gconv stays 4th launch (ncu captures launch idx 3)
    rea_repack_conv<<<dim3(16, 16), 256>>>(convW);
    rea_prep<<<(MM_*DD_ + 255)/256, 256>>>(Q);
    rea_k0<<<65, 256>>>(Wr2, Wproj, Wgate, rel, br2, bproj, bgate);
    rea_gconv<<<dim3(4, 13, 9), 256, GEMM_SMEM>>>((const float*)p_qr, (const float*)p_convWt,
                                                  convb, (float*)p_hconv);

    rea_repack_bcat<<<(512*1280 + 255)/256, 256>>>(Wq, Wk, Wc1, Wr1, bq, bk, Wv, Wo);
    rea_bn_stats<<<49, 256>>>();
    rea_eqkv<<<(MM_*DD_ + 255)/256, 256>>>(Q, Kin, Vin);

    rea_gqkv<<<dim3(10, 13, 3), 256, GEMM_SMEM>>>(bv);

    rea_pair<<<dim3(32, 5), 512>>>(Wc2, bc1, gc, bcln, bc2, br1, gr, brln);
    rea_attn<<<dim3(8, 32), 256>>>((float*)p_att, (float*)d_out);

    rea_gout<<<dim3(4, 13, 4), 256, GEMM_SMEM>>>((const float*)p_att, (const float*)p_Wor,
                                                 bo, (float*)d_out);
}

// round 7
// speedup vs baseline: 1.5367x; 1.0097x over previous
#include <cuda_runtime.h>
#include <math.h>
#include <stdint.h>

// Problem constants
#define BB_ 32
#define NN_ 49
#define DD_ 512
#define MM_ (BB_*NN_)      // 1568
#define NRELV_ 14
#define EPSV_ 1e-5f
#define SCALEV_ 0.125f     // 1/sqrt(64)

// ---------------- device scratch (no allocations allowed) ----------------
__device__ __align__(256) float g_hconv[MM_*DD_];
__device__ __align__(256) float g_qr[MM_*DD_];
__device__ __align__(256) float g_eq[MM_*DD_];
__device__ __align__(256) float g_ek[MM_*DD_];
__device__ __align__(256) float g_ev[MM_*DD_];
__device__ __align__(256) float g_eqcat[MM_*1280];
__device__ __align__(256) float g_ekcat[MM_*1280];
__device__ __align__(256) float g_v[MM_*DD_];
__device__ __align__(256) float g_att[MM_*DD_];
__device__ __align__(256) float g_convWt[9*512*512];
__device__ __align__(256) float g_Bq[512*1280];
__device__ __align__(256) float g_Bk[512*1280];
__device__ __align__(256) float g_Wvr[512*512];
__device__ __align__(256) float g_Wor[512*512];
__device__ __align__(256) float g_biasq[1280];
__device__ __align__(256) float g_biask[1280];
__device__ float g_sums[1024];
__device__ float g_wr2g[512];
__device__ float g_reg[NRELV_];
__device__ float g_c0[1];
__device__ float g_gate[MM_*NN_];

__device__ __forceinline__ float wsum(float v) {
#pragma unroll
    for (int o = 16; o > 0; o >>= 1) v += __shfl_xor_sync(0xffffffffu, v, o);
    return v;
}

__device__ __forceinline__ float to_tf32(float x) {
    uint32_t u;
    asm("cvt.rna.tf32.f32 %0, %1;" : "=r"(u) : "f"(x));
    return __uint_as_float(u);
}

__device__ __forceinline__ void mma_tf32(float* c,
                                         uint32_t a0, uint32_t a1, uint32_t a2, uint32_t a3,
                                         uint32_t b0, uint32_t b1) {
    asm volatile("mma.sync.aligned.m16n8k8.row.col.f32.tf32.tf32.f32 "
                 "{%0,%1,%2,%3}, {%4,%5,%6,%7}, {%8,%9}, {%0,%1,%2,%3};"
                 : "+f"(c[0]), "+f"(c[1]), "+f"(c[2]), "+f"(c[3])
                 : "r"(a0), "r"(a1), "r"(a2), "r"(a3), "r"(b0), "r"(b1));
}

__device__ __forceinline__ void cp16(uint32_t dst, const float* src, bool pred) {
    int sz = pred ? 16 : 0;
    asm volatile("cp.async.cg.shared.global [%0], [%1], 16, %2;\n"
                 :: "r"(dst), "l"(src), "r"(sz));
}
#define CP_COMMIT() asm volatile("cp.async.commit_group;" ::: "memory")
#define CP_WAIT1()  asm volatile("cp.async.wait_group 1;" ::: "memory")

// ---------------- folded gate vectors: parallel version ----------------
__global__ void rea_k0(const float* __restrict__ Wr2, const float* __restrict__ Wproj,
                       const float* __restrict__ Wg, const float* __restrict__ rel,
                       const float* __restrict__ br2, const float* __restrict__ bproj,
                       const float* __restrict__ bgate) {
    __shared__ float wg_s[512];
    __shared__ float wpg_s[64];
    int t = threadIdx.x;
    wg_s[t] = Wg[t];
    wg_s[t + 256] = Wg[t + 256];
    __syncthreads();
    int w = t >> 5, l = t & 31;
    if (blockIdx.x < 64) {
        int row = blockIdx.x*8 + w;
        float s = 0.f;
        for (int j = l; j < 512; j += 32) s += Wr2[(size_t)row*512 + j] * wg_s[j];
        s = wsum(s);
        if (l == 0) g_wr2g[row] = s;
    } else {
        for (int r = w; r < 64; r += 8) {
            float s = 0.f;
            for (int j = l; j < 512; j += 32) s += Wproj[(size_t)r*512 + j] * wg_s[j];
            s = wsum(s);
            if (l == 0) wpg_s[r] = s;
        }
        __syncthreads();
        if (t < NRELV_) {
            float s = 0.f;
            for (int d = 0; d < 64; d++) s += rel[t*64 + d] * wpg_s[d];
            g_reg[t] = s;
        }
        if (w == 7) {
            float s = 0.f;
            for (int j = l; j < 512; j += 32) s += (br2[j] + bproj[j]) * wg_s[j];
            s = wsum(s);
            if (l == 0) g_c0[0] = s + bgate[0];
        }
    }
}

// ---------------- conv weight repack, fully coalesced both sides ----------
__global__ void rea_repack_conv(const float* __restrict__ convW) {
    __shared__ float ts[32*289];
    int o0 = blockIdx.x*32, c0 = blockIdx.y*32;
    int t = threadIdx.x;
    for (int idx = t; idx < 32*288; idx += 256) {
        int o = idx / 288, r = idx - o*288;   // r = c_local*9 + tap
        ts[o*289 + r] = to_tf32(convW[((size_t)(o0 + o)*512 + c0)*9 + r]);
    }
    __syncthreads();
    for (int idx = t; idx < 288*32; idx += 256) {
        int row = idx >> 5, o = idx & 31;
        int c = row / 9, tap = row - c*9;
        g_convWt[(size_t)tap*262144 + (size_t)(c0 + c)*512 + o0 + o] = ts[o*289 + row];
    }
}

__global__ void rea_repack_bcat(const float* __restrict__ Wq, const float* __restrict__ Wk,
                                const float* __restrict__ Wc1, const float* __restrict__ Wr1,
                                const float* __restrict__ bq, const float* __restrict__ bk,
                                const float* __restrict__ Wv, const float* __restrict__ Wo) {
    int idx = blockIdx.x*blockDim.x + threadIdx.x;
    if (idx < 512*1280) {
        int k = idx / 1280, n = idx - k*1280;
        float vq, vk;
        if (n < 512)       { vq = Wq[(size_t)k*512 + n];              vk = Wk[(size_t)k*512 + n]; }
        else if (n < 768)  { vq = Wc1[(size_t)k*256 + (n-512)];       vk = Wc1[(size_t)(k+512)*256 + (n-512)]; }
        else               { vq = Wr1[(size_t)k*512 + (n-768)];       vk = Wr1[(size_t)(k+512)*512 + (n-768)]; }
        g_Bq[idx] = to_tf32(vq); g_Bk[idx] = to_tf32(vk);
    }
    if (idx < 512*512) {
        g_Wvr[idx] = to_tf32(Wv[idx]);
        g_Wor[idx] = to_tf32(Wo[idx]);
    }
    if (idx < 1280) {
        g_biasq[idx] = idx < 512 ? bq[idx] : 0.f;
        g_biask[idx] = idx < 512 ? bk[idx] : 0.f;
    }
}

// zero hconv/sums + round Q, one pass
__global__ void rea_prep(const float* __restrict__ Q) {
    int i = blockIdx.x*blockDim.x + threadIdx.x;
    if (i < MM_*DD_) { g_qr[i] = to_tf32(Q[i]); g_hconv[i] = 0.f; }
    if (i < 1024) g_sums[i] = 0.f;
}

// ---------------- TF32 tensor-core GEMM core ----------------
// 128 threads = 4 warps (2M x 2N), warp tile 64x64, block tile 128x128, BK=16,
// 3-stage cp.async ring. 1.0 MMA per LDS (vs 0.67 at 64x32 warp tiles).
#define BMT 128
#define BNT 128
#define BKT 16
#define APAD 20
#define BPAD 136
#define SZA (BMT*APAD*4)
#define SZB (BKT*BPAD*4)
#define GEMM_SMEM (3*(BMT*APAD + BKT*BPAD)*4)

template <bool CONV, bool ATOMIC>
__device__ __forceinline__ void gemm_core(
    const float* __restrict__ A, const float* __restrict__ Bm,
    const float* __restrict__ bias, float* __restrict__ C,
    int M, int N, int lda, int kbase, int KT, int di, int dj,
    float* AsB, float* BsB) {

    int tid = threadIdx.x;
    int lane = tid & 31, warp = tid >> 5;
    int g = lane >> 2, t4 = lane & 3;
    int wm = (warp & 1) * 64, wn = (warp >> 1) * 64;
    int m0 = blockIdx.y * BMT, n0 = blockIdx.x * BNT;

    uint32_t sA = (uint32_t)__cvta_generic_to_shared(AsB);
    uint32_t sB = (uint32_t)__cvta_generic_to_shared(BsB);

    float acc[4][8][4];
#pragma unroll
    for (int i = 0; i < 4; i++)
#pragma unroll
        for (int j = 0; j < 8; j++)
#pragma unroll
            for (int q = 0; q < 4; q++) acc[i][j][q] = 0.f;

    // hoisted per-thread load slots (4 A + 4 B chunks of 16B)
    const float* aptr[4]; bool apred[4]; uint32_t adst[4];
    const float* bptr[4]; uint32_t bdst[4];
#pragma unroll
    for (int h = 0; h < 4; h++) {
        int c = tid + h*128;
        int m = c >> 2, kg = c & 3;
        int gm = m0 + m;
        bool pred;
        const float* p;
        if (!CONV) {
            pred = gm < M;
            p = A + (size_t)(pred ? gm : 0)*lda + kbase + kg*4;
        } else {
            int bb = gm / 49, pos = gm - bb*49;
            int pr = pos / 7, pc = pos - pr*7;
            int ii = pr + di, jj = pc + dj;
            pred = (gm < M) & ((unsigned)ii < 7u) & ((unsigned)jj < 7u);
            p = pred ? (A + ((size_t)(bb*49 + ii*7 + jj))*512 + kg*4) : A;
        }
        apred[h] = pred; aptr[h] = p;
        adst[h] = sA + (uint32_t)(m*APAD + kg*4)*4;
        int kr = c >> 5, ng = c & 31;
        bptr[h] = Bm + (size_t)(kbase + kr)*N + n0 + ng*4;
        bdst[h] = sB + (uint32_t)(kr*BPAD + ng*4)*4;
    }

    auto load_tile = [&](int kt, int buf) {
#pragma unroll
        for (int h = 0; h < 4; h++)
            cp16(adst[h] + buf*SZA, aptr[h] + kt*BKT, apred[h]);
#pragma unroll
        for (int h = 0; h < 4; h++)
            cp16(bdst[h] + buf*SZB, bptr[h] + (size_t)kt*BKT*N, true);
    };

    load_tile(0, 0); CP_COMMIT();
    if (KT > 1) load_tile(1, 1);
    CP_COMMIT();

    int buf = 0, nbuf = 2;
    for (int kt = 0; kt < KT; kt++) {
        CP_WAIT1();
        __syncthreads();
        if (kt + 2 < KT) load_tile(kt + 2, nbuf);
        CP_COMMIT();
        const float* as = AsB + buf*(BMT*APAD);
        const float* bs = BsB + buf*(BKT*BPAD);
#pragma unroll
        for (int k8 = 0; k8 < 2; k8++) {
            uint32_t af[4][4], bf[8][2];
#pragma unroll
            for (int i = 0; i < 4; i++) {
                int mrow = wm + i*16 + g;
                af[i][0] = __float_as_uint(as[mrow*APAD + k8*8 + t4]);
                af[i][1] = __float_as_uint(as[(mrow + 8)*APAD + k8*8 + t4]);
                af[i][2] = __float_as_uint(as[mrow*APAD + k8*8 + t4 + 4]);
                af[i][3] = __float_as_uint(as[(mrow + 8)*APAD + k8*8 + t4 + 4]);
            }
#pragma unroll
            for (int j = 0; j < 8; j++) {
                int nc = wn + j*8 + g;
                bf[j][0] = __float_as_uint(bs[(k8*8 + t4)*BPAD + nc]);
                bf[j][1] = __float_as_uint(bs[(k8*8 + t4 + 4)*BPAD + nc]);
            }
#pragma unroll
            for (int i = 0; i < 4; i++)
#pragma unroll
                for (int j = 0; j < 8; j++)
                    mma_tf32(acc[i][j], af[i][0], af[i][1], af[i][2], af[i][3],
                             bf[j][0], bf[j][1]);
        }
        buf = (buf == 2) ? 0 : buf + 1;
        nbuf = (nbuf == 2) ? 0 : nbuf + 1;
    }

#pragma unroll
    for (int i = 0; i < 4; i++) {
        int mbase = m0 + wm + i*16 + g;
#pragma unroll
        for (int half = 0; half < 2; half++) {
            int gm = mbase + half*8;
            if (gm < M) {
#pragma unroll
                for (int j = 0; j < 8; j++) {
                    int gn = n0 + wn + j*8 + t4*2;
                    float v0 = acc[i][j][half*2 + 0];
                    float v1 = acc[i][j][half*2 + 1];
                    if (ATOMIC) {
                        if (blockIdx.z == 0 && bias) { v0 += bias[gn]; v1 += bias[gn + 1]; }
                        atomicAdd(&C[(size_t)gm*N + gn],     v0);
                        atomicAdd(&C[(size_t)gm*N + gn + 1], v1);
                    } else {
                        if (bias) { v0 += bias[gn]; v1 += bias[gn + 1]; }
                        C[(size_t)gm*N + gn]     = v0;
                        C[(size_t)gm*N + gn + 1] = v1;
                    }
                }
            }
        }
    }
}

extern __shared__ float sm_gemm[];

// conv as implicit GEMM, split-K=9 (one tap per z), atomic accumulate
__global__ void __launch_bounds__(128, 2)
rea_gconv(const float* __restrict__ A, const float* __restrict__ Bm,
          const float* __restrict__ bias, float* __restrict__ C) {
    int tap = blockIdx.z;
    gemm_core<true, true>(A, Bm, bias, C, MM_, 512, 512,
                          tap*512, 32, tap/3 - 1, tap%3 - 1,
                          sm_gemm, sm_gemm + 3*BMT*APAD);
}

__global__ void __launch_bounds__(128, 2)
rea_gqkv(const float* __restrict__ bv) {
    int z = blockIdx.z;
    if (z == 2 && blockIdx.x >= 4) return;
    const float* A    = z == 0 ? g_eq    : z == 1 ? g_ek    : g_ev;
    const float* Bm   = z == 0 ? g_Bq    : z == 1 ? g_Bk    : g_Wvr;
    const float* bias = z == 0 ? g_biasq : z == 1 ? g_biask : bv;
    float*       C    = z == 0 ? g_eqcat : z == 1 ? g_ekcat : g_v;
    int N = z < 2 ? 1280 : 512;
    gemm_core<false, false>(A, Bm, bias, C, MM_, N, 512, 0, 32, 0, 0,
                            sm_gemm, sm_gemm + 3*BMT*APAD);
}

// output projection, split-K=4, atomic into pre-zeroed d_out
__global__ void __launch_bounds__(128, 2)
rea_gout(const float* __restrict__ A, const float* __restrict__ Bm,
         const float* __restrict__ bias, float* __restrict__ C) {
    gemm_core<false, true>(A, Bm, bias, C, MM_, 512, 512,
                           blockIdx.z*128, 8, 0, 0,
                           sm_gemm, sm_gemm + 3*BMT*APAD);
}

// ---------------- batchnorm stats + eq/ek/ev (bn finalize inlined) ----------
__global__ void rea_bn_stats() {
    __shared__ float ss[512], sq[512];
    int tid = threadIdx.x;
    for (int c = tid; c < 512; c += 256) { ss[c] = 0.f; sq[c] = 0.f; }
    __syncthreads();
    int r0 = blockIdx.x*32;
    for (int r = r0; r < r0 + 32; r++) {
        for (int c = tid; c < 512; c += 256) {
            float v = g_hconv[(size_t)r*512 + c];
            ss[c] += v; sq[c] += v*v;
        }
    }
    __syncthreads();
    for (int c = tid; c < 512; c += 256) {
        atomicAdd(&g_sums[c], ss[c]);
        atomicAdd(&g_sums[512 + c], sq[c]);
    }
}

__global__ void rea_eqkv(const float* __restrict__ Q, const float* __restrict__ Kin,
                         const float* __restrict__ Vin) {
    int idx = blockIdx.x*blockDim.x + threadIdx.x;
    if (idx >= MM_*DD_) return;
    int c = idx & 511;
    float mu = g_sums[c] * (1.f/1568.f);
    float var = g_sums[512 + c] * (1.f/1568.f) - mu*mu;
    float isd = rsqrtf(var + EPSV_);
    float xn = (g_hconv[idx] - mu) * isd;
    xn = fmaxf(xn, 0.f);
    g_eq[idx] = to_tf32(xn + Q[idx]);
    g_ek[idx] = to_tf32(xn + Kin[idx]);
    g_ev[idx] = to_tf32(xn + Vin[idx]);
}

// ---------------- per-pair gate: one pair per LANE, j-dim tiled in smem ------
#define PTILE 64
__global__ void __launch_bounds__(512)
rea_pair(const float* __restrict__ Wc2, const float* __restrict__ bc1,
         const float* __restrict__ gc, const float* __restrict__ bcln,
         const float* __restrict__ bc2, const float* __restrict__ br1,
         const float* __restrict__ gr, const float* __restrict__ brln) {
    __shared__ float ck_s[PTILE*49];
    __shared__ float pq_s[PTILE*49];
    __shared__ float wct_s[PTILE*16];
    __shared__ float2 ab_s[PTILE];
    __shared__ float w2_s[PTILE];
    __shared__ float s_bc2[16], s_reg[16];

    int b = blockIdx.x;
    int t = threadIdx.x;
    int p = blockIdx.y*512 + t;
    int q = p / 49, k = p - q*49;
    bool act = q < 49;
    int qc = act ? q : 48;
    int b49 = b*49;

    if (t < NRELV_) { s_bc2[t] = bc2[t]; s_reg[t] = g_reg[t]; }
    if (t < PTILE) { wct_s[t*16 + 14] = 0.f; wct_s[t*16 + 15] = 0.f; }

    // ======== channel branch (256 dims, offset 512) ========
    float s1 = 0.f, s2 = 0.f;
    for (int jt = 0; jt < 4; jt++) {
        int j0 = jt*PTILE;
        __syncthreads();
        for (int idx = t; idx < PTILE*49; idx += 512) {
            int kk = idx >> 6, j = idx & 63;
            size_t base = (size_t)(b49 + kk)*1280 + 512 + j0 + j;
            ck_s[j*49 + kk] = g_ekcat[base];
            pq_s[j*49 + kk] = g_eqcat[base] + bc1[j0 + j];
        }
        __syncthreads();
#pragma unroll 8
        for (int j = 0; j < PTILE; j++) {
            float xc = pq_s[j*49 + qc] + ck_s[j*49 + k];
            s1 += xc; s2 = fmaf(xc, xc, s2);
        }
    }
    float mu = s1 * (1.f/256.f);
    float rs = rsqrtf(s2*(1.f/256.f) - mu*mu + EPSV_);

    float lg[14];
#pragma unroll
    for (int i = 0; i < 14; i++) lg[i] = 0.f;
    for (int jt = 0; jt < 4; jt++) {
        int j0 = jt*PTILE;
        __syncthreads();
        for (int idx = t; idx < PTILE*49; idx += 512) {
            int kk = idx >> 6, j = idx & 63;
            size_t base = (size_t)(b49 + kk)*1280 + 512 + j0 + j;
            ck_s[j*49 + kk] = g_ekcat[base];
            pq_s[j*49 + kk] = g_eqcat[base] + bc1[j0 + j];
        }
        for (int idx = t; idx < PTILE*14; idx += 512) {
            int j = idx / 14, tt = idx - j*14;
            wct_s[j*16 + tt] = Wc2[(size_t)(j0 + j)*14 + tt];
        }
        if (t < PTILE) ab_s[t] = make_float2(gc[j0 + t], bcln[j0 + t]);
        __syncthreads();
#pragma unroll 4
        for (int j = 0; j < PTILE; j++) {
            float xc = pq_s[j*49 + qc] + ck_s[j*49 + k];
            float2 ab = ab_s[j];
            float A = rs * ab.x;
            float y = fmaxf(fmaf(xc, A, ab.y - mu*A), 0.f);
            const float4* w4 = (const float4*)&wct_s[j*16];
            float4 w0 = w4[0], w1 = w4[1], w2v = w4[2], w3v = w4[3];
            lg[0]  = fmaf(y, w0.x,  lg[0]);  lg[1]  = fmaf(y, w0.y,  lg[1]);
            lg[2]  = fmaf(y, w0.z,  lg[2]);  lg[3]  = fmaf(y, w0.w,  lg[3]);
            lg[4]  = fmaf(y, w1.x,  lg[4]);  lg[5]  = fmaf(y, w1.y,  lg[5]);
            lg[6]  = fmaf(y, w1.z,  lg[6]);  lg[7]  = fmaf(y, w1.w,  lg[7]);
            lg[8]  = fmaf(y, w2v.x, lg[8]);  lg[9]  = fmaf(y, w2v.y, lg[9]);
            lg[10] = fmaf(y, w2v.z, lg[10]); lg[11] = fmaf(y, w2v.w, lg[11]);
            lg[12] = fmaf(y, w3v.x, lg[12]); lg[13] = fmaf(y, w3v.y, lg[13]);
        }
    }
    float mx = -1e30f;
#pragma unroll
    for (int tt = 0; tt < 14; tt++) { lg[tt] += s_bc2[tt]; mx = fmaxf(mx, lg[tt]); }
    float se = 0.f, dg = 0.f;
#pragma unroll
    for (int tt = 0; tt < 14; tt++) { float e = expf(lg[tt] - mx); se += e; dg += e*s_reg[tt]; }
    float proj = dg / se * (1.f/(1.f + 1e-8f));

    // ======== relation branch (512 dims, offset 768) ========
    s1 = 0.f; s2 = 0.f;
    for (int jt = 0; jt < 8; jt++) {
        int j0 = jt*PTILE;
        __syncthreads();
        for (int idx = t; idx < PTILE*49; idx += 512) {
            int kk = idx >> 6, j = idx & 63;
            size_t base = (size_t)(b49 + kk)*1280 + 768 + j0 + j;
            ck_s[j*49 + kk] = g_ekcat[base];
            pq_s[j*49 + kk] = g_eqcat[base] + br1[j0 + j];
        }
        __syncthreads();
#pragma unroll 8
        for (int j = 0; j < PTILE; j++) {
            float xr = pq_s[j*49 + qc] + ck_s[j*49 + k];
            s1 += xr; s2 = fmaf(xr, xr, s2);
        }
    }
    float mur = s1 * (1.f/512.f);
    float rsr = rsqrtf(s2*(1.f/512.f) - mur*mur + EPSV_);

    float dr = 0.f;
    for (int jt = 0; jt < 8; jt++) {
        int j0 = jt*PTILE;
        __syncthreads();
        for (int idx = t; idx < PTILE*49; idx += 512) {
            int kk = idx >> 6, j = idx & 63;
            size_t base = (size_t)(b49 + kk)*1280 + 768 + j0 + j;
            ck_s[j*49 + kk] = g_ekcat[base];
            pq_s[j*49 + kk] = g_eqcat[base] + br1[j0 + j];
        }
        if (t < PTILE) {
            ab_s[t] = make_float2(gr[j0 + t], brln[j0 + t]);
            w2_s[t] = g_wr2g[j0 + t];
        }
        __syncthreads();
#pragma unroll 8
        for (int j = 0; j < PTILE; j++) {
            float xr = pq_s[j*49 + qc] + ck_s[j*49 + k];
            float2 ab = ab_s[j];
            float A = rsr * ab.x;
            float y = fmaxf(fmaf(xr, A, ab.y - mur*A), 0.f);
            dr = fmaf(y, w2_s[j], dr);
        }
    }

    if (act) {
        float ga = dr + proj + g_c0[0];
        g_gate[(size_t)(b49 + q)*49 + k] = 1.f/(1.f + expf(-ga));
    }
}

// ---------------- attention per (b,h); also zeroes d_out for atomic gout ----
__global__ void __launch_bounds__(256)
rea_attn(float* __restrict__ out, float* __restrict__ dz) {
    __shared__ float Qt[49*65], Kt[49*65], Vt[49*65];
    __shared__ float wrow[8][52];
    int h = blockIdx.x, b = blockIdx.y;
    int t = threadIdx.x, w = t >> 5, l = t & 31;

    {
        float4 z4 = make_float4(0.f, 0.f, 0.f, 0.f);
        float4* dst = (float4*)dz + (size_t)(b*8 + h)*784;
        for (int i = t; i < 784; i += 256) dst[i] = z4;
    }

    for (int idx = t; idx < 49*64; idx += 256) {
        int q = idx >> 6, d = idx & 63;
        Qt[q*65 + d] = g_eqcat[(size_t)(b*49 + q)*1280 + h*64 + d];
        Kt[q*65 + d] = g_ekcat[(size_t)(b*49 + q)*1280 + h*64 + d];
        Vt[q*65 + d] = g_v[(size_t)(b*49 + q)*512 + h*64 + d];
    }
    __syncthreads();

    for (int q = w; q < 49; q += 8) {
        int m = b*49 + q;
        int k2 = l + 32;
        bool v2 = k2 < 49;
        float g1 = g_gate[(size_t)m*49 + l];
        float g2 = v2 ? g_gate[(size_t)m*49 + k2] : 0.f;
        const float* qr  = Qt + q*65;
        const float* k1r = Kt + l*65;
        const float* k2r = Kt + (v2 ? k2 : l)*65;
        float d1 = 0.f, d2 = 0.f;
#pragma unroll 8
        for (int d = 0; d < 64; d++) {
            float qv = qr[d];
            d1 += qv * k1r[d];
            d2 += qv * k2r[d];
        }
        float lv1 = d1*SCALEV_*(1.f + g1);
        float lv2 = v2 ? d2*SCALEV_*(1.f + g2) : -1e30f;
        float mx = fmaxf(lv1, lv2);
#pragma unroll
        for (int o = 16; o > 0; o >>= 1) mx = fmaxf(mx, __shfl_xor_sync(0xffffffffu, mx, o));
        float e1 = expf(lv1 - mx);
        float e2 = v2 ? expf(lv2 - mx) : 0.f;
        float ssum = wsum(e1 + e2);
        float inv = 1.f / ssum;
        wrow[w][l] = e1 * inv;
        if (v2) wrow[w][k2] = e2 * inv;
        __syncwarp();
        float a1 = 0.f, a2 = 0.f;
        for (int k = 0; k < 49; k++) {
            float wk = wrow[w][k];
            a1 += wk * Vt[k*65 + l];
            a2 += wk * Vt[k*65 + l + 32];
        }
        out[(size_t)m*512 + h*64 + l]      = to_tf32(a1);
        out[(size_t)m*512 + h*64 + l + 32] = to_tf32(a2);
        __syncwarp();
    }
}

// ---------------- launch ----------------
extern "C" void kernel_launch(void* const* d_in, const int* in_sizes, int n_in,
                              void* d_out, int out_size) {
    const float* Q     = (const float*)d_in[0];
    const float* Kin   = (const float*)d_in[1];
    const float* Vin   = (const float*)d_in[2];
    const float* Wq    = (const float*)d_in[3];
    const float* bq    = (const float*)d_in[4];
    const float* Wk    = (const float*)d_in[5];
    const float* bk    = (const float*)d_in[6];
    const float* Wv    = (const float*)d_in[7];
    const float* bv    = (const float*)d_in[8];
    const float* Wo    = (const float*)d_in[9];
    const float* bo    = (const float*)d_in[10];
    const float* rel   = (const float*)d_in[11];
    const float* Wproj = (const float*)d_in[12];
    const float* bproj = (const float*)d_in[13];
    const float* Wgate = (const float*)d_in[14];
    const float* bgate = (const float*)d_in[15];
    const float* Wc1   = (const float*)d_in[16];
    const float* bc1   = (const float*)d_in[17];
    const float* gc    = (const float*)d_in[18];
    const float* bcln  = (const float*)d_in[19];
    const float* Wc2   = (const float*)d_in[20];
    const float* bc2   = (const float*)d_in[21];
    const float* Wr1   = (const float*)d_in[22];
    const float* br1   = (const float*)d_in[23];
    const float* gr    = (const float*)d_in[24];
    const float* brln  = (const float*)d_in[25];
    const float* Wr2   = (const float*)d_in[26];
    const float* br2   = (const float*)d_in[27];
    const float* convW = (const float*)d_in[28];
    const float* convb = (const float*)d_in[29];

    void *p_hconv, *p_qr, *p_att, *p_convWt, *p_Wor;
    cudaGetSymbolAddress(&p_hconv, g_hconv);
    cudaGetSymbolAddress(&p_qr, g_qr);
    cudaGetSymbolAddress(&p_att, g_att);
    cudaGetSymbolAddress(&p_convWt, g_convWt);
    cudaGetSymbolAddress(&p_Wor, g_Wor);

    static bool attr_set = false;
    if (!attr_set) {
        cudaFuncSetAttribute(rea_gconv, cudaFuncAttributeMaxDynamicSharedMemorySize, GEMM_SMEM);
        cudaFuncSetAttribute(rea_gqkv, cudaFuncAttributeMaxDynamicSharedMemorySize, GEMM_SMEM);
        cudaFuncSetAttribute(rea_gout, cudaFuncAttributeMaxDynamicSharedMemorySize, GEMM_SMEM);
        attr_set = true;
    }

    // gconv stays 4th launch (ncu captures launch idx 3)
    rea_repack_conv<<<dim3(16, 16), 256>>>(convW);
    rea_prep<<<(MM_*DD_ + 255)/256, 256>>>(Q);
    rea_k0<<<65, 256>>>(Wr2, Wproj, Wgate, rel, br2, bproj, bgate);
    rea_gconv<<<dim3(4, 13, 9), 128, GEMM_SMEM>>>((const float*)p_qr, (const float*)p_convWt,
                                                  convb, (float*)p_hconv);

    rea_repack_bcat<<<(512*1280 + 255)/256, 256>>>(Wq, Wk, Wc1, Wr1, bq, bk, Wv, Wo);
    rea_bn_stats<<<49, 256>>>();
    rea_eqkv<<<(MM_*DD_ + 255)/256, 256>>>(Q, Kin, Vin);

    rea_gqkv<<<dim3(10, 13, 3), 128, GEMM_SMEM>>>(bv);

    rea_pair<<<dim3(32, 5), 512>>>(Wc2, bc1, gc, bcln, bc2, br1, gr, brln);
    rea_attn<<<dim3(8, 32), 256>>>((float*)p_att, (float*)d_out);

    rea_gout<<<dim3(4, 13, 4), 128, GEMM_SMEM>>>((const float*)p_att, (const float*)p_Wor,
                                                 bo, (float*)d_out);
}

// round 8
// speedup vs baseline: 1.5843x; 1.0310x over previous
#include <cuda_runtime.h>
#include <math.h>
#include <stdint.h>

// Problem constants
#define BB_ 32
#define NN_ 49
#define DD_ 512
#define MM_ (BB_*NN_)      // 1568
#define NRELV_ 14
#define EPSV_ 1e-5f
#define SCALEV_ 0.125f     // 1/sqrt(64)

// ---------------- device scratch (no allocations allowed) ----------------
__device__ __align__(256) float g_hconv[MM_*DD_];
__device__ __align__(256) float g_qr[MM_*DD_];
__device__ __align__(256) float g_eq[MM_*DD_];
__device__ __align__(256) float g_ek[MM_*DD_];
__device__ __align__(256) float g_ev[MM_*DD_];
__device__ __align__(256) float g_eqcat[MM_*1280];
__device__ __align__(256) float g_ekcat[MM_*1280];
__device__ __align__(256) float g_v[MM_*DD_];
__device__ __align__(256) float g_att[MM_*DD_];
__device__ __align__(256) float g_convWt[9*512*512];
__device__ __align__(256) float g_Bq[512*1280];
__device__ __align__(256) float g_Bk[512*1280];
__device__ __align__(256) float g_Wvr[512*512];
__device__ __align__(256) float g_Wor[512*512];
__device__ __align__(256) float g_biasq[1280];
__device__ __align__(256) float g_biask[1280];
__device__ float g_sums[1024];
__device__ float g_wr2g[512];
__device__ float g_reg[NRELV_];
__device__ float g_c0[1];
__device__ float g_gate[MM_*NN_];

__device__ __forceinline__ float wsum(float v) {
#pragma unroll
    for (int o = 16; o > 0; o >>= 1) v += __shfl_xor_sync(0xffffffffu, v, o);
    return v;
}

__device__ __forceinline__ float to_tf32(float x) {
    uint32_t u;
    asm("cvt.rna.tf32.f32 %0, %1;" : "=r"(u) : "f"(x));
    return __uint_as_float(u);
}

__device__ __forceinline__ void mma_tf32(float* c,
                                         uint32_t a0, uint32_t a1, uint32_t a2, uint32_t a3,
                                         uint32_t b0, uint32_t b1) {
    asm volatile("mma.sync.aligned.m16n8k8.row.col.f32.tf32.tf32.f32 "
                 "{%0,%1,%2,%3}, {%4,%5,%6,%7}, {%8,%9}, {%0,%1,%2,%3};"
                 : "+f"(c[0]), "+f"(c[1]), "+f"(c[2]), "+f"(c[3])
                 : "r"(a0), "r"(a1), "r"(a2), "r"(a3), "r"(b0), "r"(b1));
}

__device__ __forceinline__ void cp16(uint32_t dst, const float* src, bool pred) {
    int sz = pred ? 16 : 0;
    asm volatile("cp.async.cg.shared.global [%0], [%1], 16, %2;\n"
                 :: "r"(dst), "l"(src), "r"(sz));
}
#define CP_COMMIT() asm volatile("cp.async.commit_group;" ::: "memory")
#define CP_WAIT1()  asm volatile("cp.async.wait_group 1;" ::: "memory")

// ---------------- folded gate vectors: parallel version ----------------
__global__ void rea_k0(const float* __restrict__ Wr2, const float* __restrict__ Wproj,
                       const float* __restrict__ Wg, const float* __restrict__ rel,
                       const float* __restrict__ br2, const float* __restrict__ bproj,
                       const float* __restrict__ bgate) {
    __shared__ float wg_s[512];
    __shared__ float wpg_s[64];
    int t = threadIdx.x;
    wg_s[t] = Wg[t];
    wg_s[t + 256] = Wg[t + 256];
    __syncthreads();
    int w = t >> 5, l = t & 31;
    if (blockIdx.x < 64) {
        int row = blockIdx.x*8 + w;
        float s = 0.f;
        for (int j = l; j < 512; j += 32) s += Wr2[(size_t)row*512 + j] * wg_s[j];
        s = wsum(s);
        if (l == 0) g_wr2g[row] = s;
    } else {
        for (int r = w; r < 64; r += 8) {
            float s = 0.f;
            for (int j = l; j < 512; j += 32) s += Wproj[(size_t)r*512 + j] * wg_s[j];
            s = wsum(s);
            if (l == 0) wpg_s[r] = s;
        }
        __syncthreads();
        if (t < NRELV_) {
            float s = 0.f;
            for (int d = 0; d < 64; d++) s += rel[t*64 + d] * wpg_s[d];
            g_reg[t] = s;
        }
        if (w == 7) {
            float s = 0.f;
            for (int j = l; j < 512; j += 32) s += (br2[j] + bproj[j]) * wg_s[j];
            s = wsum(s);
            if (l == 0) g_c0[0] = s + bgate[0];
        }
    }
}

// ---------------- fused prologue: conv repack + Q round/zero + sums zero ----
__global__ void rea_pre(const float* __restrict__ convW, const float* __restrict__ Q) {
    __shared__ float ts[32*289];
    int bx = blockIdx.x, t = threadIdx.x;
    if (bx < 256) {
        int o0 = (bx & 15)*32, c0 = (bx >> 4)*32;
        for (int idx = t; idx < 32*288; idx += 256) {
            int o = idx / 288, r = idx - o*288;   // r = c_local*9 + tap
            ts[o*289 + r] = to_tf32(convW[((size_t)(o0 + o)*512 + c0)*9 + r]);
        }
        __syncthreads();
        for (int idx = t; idx < 288*32; idx += 256) {
            int row = idx >> 5, o = idx & 31;
            int c = row / 9, tap = row - c*9;
            g_convWt[(size_t)tap*262144 + (size_t)(c0 + c)*512 + o0 + o] = ts[o*289 + row];
        }
    } else {
        int idx = (bx - 256)*256 + t;  // float4 index
        if (idx < MM_*DD_/4) {
            float4 qv = ((const float4*)Q)[idx];
            float4 r;
            r.x = to_tf32(qv.x); r.y = to_tf32(qv.y);
            r.z = to_tf32(qv.z); r.w = to_tf32(qv.w);
            ((float4*)g_qr)[idx] = r;
            ((float4*)g_hconv)[idx] = make_float4(0.f, 0.f, 0.f, 0.f);
        }
        if (bx == 256 && t < 256)
            ((float4*)g_sums)[t] = make_float4(0.f, 0.f, 0.f, 0.f);
    }
}

__global__ void rea_repack_bcat(const float* __restrict__ Wq, const float* __restrict__ Wk,
                                const float* __restrict__ Wc1, const float* __restrict__ Wr1,
                                const float* __restrict__ bq, const float* __restrict__ bk,
                                const float* __restrict__ Wv, const float* __restrict__ Wo) {
    int idx = blockIdx.x*blockDim.x + threadIdx.x;
    if (idx < 512*1280) {
        int k = idx / 1280, n = idx - k*1280;
        float vq, vk;
        if (n < 512)       { vq = Wq[(size_t)k*512 + n];              vk = Wk[(size_t)k*512 + n]; }
        else if (n < 768)  { vq = Wc1[(size_t)k*256 + (n-512)];       vk = Wc1[(size_t)(k+512)*256 + (n-512)]; }
        else               { vq = Wr1[(size_t)k*512 + (n-768)];       vk = Wr1[(size_t)(k+512)*512 + (n-768)]; }
        g_Bq[idx] = to_tf32(vq); g_Bk[idx] = to_tf32(vk);
    }
    if (idx < 512*512) {
        g_Wvr[idx] = to_tf32(Wv[idx]);
        g_Wor[idx] = to_tf32(Wo[idx]);
    }
    if (idx < 1280) {
        g_biasq[idx] = idx < 512 ? bq[idx] : 0.f;
        g_biask[idx] = idx < 512 ? bk[idx] : 0.f;
    }
}

// ---------------- TF32 tensor-core GEMM core ----------------
// 128 threads = 4 warps (2M x 2N), warp tile 64x64, block tile 128x128, BK=32,
// 3-stage cp.async ring. 128 MMAs per warp between syncs.
#define BMT 128
#define BNT 128
#define BKT 32
#define APAD 36
#define BPAD 136
#define SZA (BMT*APAD*4)
#define SZB (BKT*BPAD*4)
#define GEMM_SMEM (3*(BMT*APAD + BKT*BPAD)*4)

template <bool CONV, bool ATOMIC>
__device__ __forceinline__ void gemm_core(
    const float* __restrict__ A, const float* __restrict__ Bm,
    const float* __restrict__ bias, float* __restrict__ C,
    int M, int N, int lda, int kbase, int KT, int di, int dj,
    int m0, int n0, int zz,
    float* AsB, float* BsB) {

    int tid = threadIdx.x;
    int lane = tid & 31, warp = tid >> 5;
    int g = lane >> 2, t4 = lane & 3;
    int wm = (warp & 1) * 64, wn = (warp >> 1) * 64;

    uint32_t sA = (uint32_t)__cvta_generic_to_shared(AsB);
    uint32_t sB = (uint32_t)__cvta_generic_to_shared(BsB);

    float acc[4][8][4];
#pragma unroll
    for (int i = 0; i < 4; i++)
#pragma unroll
        for (int j = 0; j < 8; j++)
#pragma unroll
            for (int q = 0; q < 4; q++) acc[i][j][q] = 0.f;

    // hoisted per-thread load slots (8 A + 8 B chunks of 16B per k-tile)
    const float* aptr[8]; bool apred[8]; uint32_t adst[8];
    const float* bptr0; uint32_t bdst0;
#pragma unroll
    for (int h = 0; h < 8; h++) {
        int c = tid + h*128;
        int m = c >> 3, kg = c & 7;
        int gm = m0 + m;
        bool pred;
        const float* p;
        if (!CONV) {
            pred = gm < M;
            p = A + (size_t)(pred ? gm : 0)*lda + kbase + kg*4;
        } else {
            int bb = gm / 49, pos = gm - bb*49;
            int pr = pos / 7, pc = pos - pr*7;
            int ii = pr + di, jj = pc + dj;
            pred = (gm < M) & ((unsigned)ii < 7u) & ((unsigned)jj < 7u);
            p = pred ? (A + ((size_t)(bb*49 + ii*7 + jj))*512 + kg*4) : A;
        }
        apred[h] = pred; aptr[h] = p;
        adst[h] = sA + (uint32_t)(m*APAD + kg*4)*4;
    }
    {
        int kr = tid >> 5, ng = tid & 31;
        bptr0 = Bm + (size_t)(kbase + kr)*N + n0 + ng*4;
        bdst0 = sB + (uint32_t)(kr*BPAD + ng*4)*4;
    }

    auto load_tile = [&](int kt, int buf) {
#pragma unroll
        for (int h = 0; h < 8; h++)
            cp16(adst[h] + buf*SZA, aptr[h] + kt*BKT, apred[h]);
#pragma unroll
        for (int h = 0; h < 8; h++)
            cp16(bdst0 + buf*SZB + (uint32_t)h*4*BPAD*4,
                 bptr0 + (size_t)(kt*BKT + h*4)*N, true);
    };

    load_tile(0, 0); CP_COMMIT();
    if (KT > 1) load_tile(1, 1);
    CP_COMMIT();

    int buf = 0, nbuf = 2;
    for (int kt = 0; kt < KT; kt++) {
        CP_WAIT1();
        __syncthreads();
        if (kt + 2 < KT) load_tile(kt + 2, nbuf);
        CP_COMMIT();
        const float* as = AsB + buf*(BMT*APAD);
        const float* bs = BsB + buf*(BKT*BPAD);
#pragma unroll
        for (int k8 = 0; k8 < 4; k8++) {
            uint32_t af[4][4], bf[8][2];
#pragma unroll
            for (int i = 0; i < 4; i++) {
                int mrow = wm + i*16 + g;
                af[i][0] = __float_as_uint(as[mrow*APAD + k8*8 + t4]);
                af[i][1] = __float_as_uint(as[(mrow + 8)*APAD + k8*8 + t4]);
                af[i][2] = __float_as_uint(as[mrow*APAD + k8*8 + t4 + 4]);
                af[i][3] = __float_as_uint(as[(mrow + 8)*APAD + k8*8 + t4 + 4]);
            }
#pragma unroll
            for (int j = 0; j < 8; j++) {
                int nc = wn + j*8 + g;
                bf[j][0] = __float_as_uint(bs[(k8*8 + t4)*BPAD + nc]);
                bf[j][1] = __float_as_uint(bs[(k8*8 + t4 + 4)*BPAD + nc]);
            }
#pragma unroll
            for (int i = 0; i < 4; i++)
#pragma unroll
                for (int j = 0; j < 8; j++)
                    mma_tf32(acc[i][j], af[i][0], af[i][1], af[i][2], af[i][3],
                             bf[j][0], bf[j][1]);
        }
        buf = (buf == 2) ? 0 : buf + 1;
        nbuf = (nbuf == 2) ? 0 : nbuf + 1;
    }

#pragma unroll
    for (int i = 0; i < 4; i++) {
        int mbase = m0 + wm + i*16 + g;
#pragma unroll
        for (int half = 0; half < 2; half++) {
            int gm = mbase + half*8;
            if (gm < M) {
#pragma unroll
                for (int j = 0; j < 8; j++) {
                    int gn = n0 + wn + j*8 + t4*2;
                    float v0 = acc[i][j][half*2 + 0];
                    float v1 = acc[i][j][half*2 + 1];
                    if (ATOMIC) {
                        if (zz == 0 && bias) { v0 += bias[gn]; v1 += bias[gn + 1]; }
                        atomicAdd(&C[(size_t)gm*N + gn],     v0);
                        atomicAdd(&C[(size_t)gm*N + gn + 1], v1);
                    } else {
                        if (bias) { v0 += bias[gn]; v1 += bias[gn + 1]; }
                        C[(size_t)gm*N + gn]     = v0;
                        C[(size_t)gm*N + gn + 1] = v1;
                    }
                }
            }
        }
    }
}

extern __shared__ float sm_gemm[];

// conv as implicit GEMM, split-K=9 (one tap per z), atomic accumulate
__global__ void __launch_bounds__(128, 2)
rea_gconv(const float* __restrict__ A, const float* __restrict__ Bm,
          const float* __restrict__ bias, float* __restrict__ C) {
    int tap = blockIdx.z;
    gemm_core<true, true>(A, Bm, bias, C, MM_, 512, 512,
                          tap*512, 16, tap/3 - 1, tap%3 - 1,
                          blockIdx.y*BMT, blockIdx.x*BNT, tap,
                          sm_gemm, sm_gemm + 3*BMT*APAD);
}

// batched eq/ek/ev projections, flat 312-block grid (no dead CTAs)
__global__ void __launch_bounds__(128, 2)
rea_gqkv(const float* __restrict__ bv) {
    int bx = blockIdx.x;
    int z, lx;
    if (bx < 130)      { z = 0; lx = bx; }
    else if (bx < 260) { z = 1; lx = bx - 130; }
    else               { z = 2; lx = bx - 260; }
    int m0, n0;
    if (z < 2) { n0 = (lx % 10)*BNT; m0 = (lx / 10)*BMT; }
    else       { n0 = (lx & 3)*BNT;  m0 = (lx >> 2)*BMT; }
    const float* A    = z == 0 ? g_eq    : z == 1 ? g_ek    : g_ev;
    const float* Bm   = z == 0 ? g_Bq    : z == 1 ? g_Bk    : g_Wvr;
    const float* bias = z == 0 ? g_biasq : z == 1 ? g_biask : bv;
    float*       C    = z == 0 ? g_eqcat : z == 1 ? g_ekcat : g_v;
    int N = z < 2 ? 1280 : 512;
    gemm_core<false, false>(A, Bm, bias, C, MM_, N, 512, 0, 16, 0, 0,
                            m0, n0, 0, sm_gemm, sm_gemm + 3*BMT*APAD);
}

// output projection, split-K=4, atomic into pre-zeroed d_out
__global__ void __launch_bounds__(128, 2)
rea_gout(const float* __restrict__ A, const float* __restrict__ Bm,
         const float* __restrict__ bias, float* __restrict__ C) {
    gemm_core<false, true>(A, Bm, bias, C, MM_, 512, 512,
                           blockIdx.z*128, 4, 0, 0,
                           blockIdx.y*BMT, blockIdx.x*BNT, blockIdx.z,
                           sm_gemm, sm_gemm + 3*BMT*APAD);
}

// ---------------- batchnorm stats + eq/ek/ev (bn finalize inlined) ----------
__global__ void rea_bn_stats() {
    __shared__ float ss[512], sq[512];
    int tid = threadIdx.x;
    for (int c = tid; c < 512; c += 256) { ss[c] = 0.f; sq[c] = 0.f; }
    __syncthreads();
    int r0 = blockIdx.x*32;
    for (int r = r0; r < r0 + 32; r++) {
        for (int c = tid; c < 512; c += 256) {
            float v = g_hconv[(size_t)r*512 + c];
            ss[c] += v; sq[c] += v*v;
        }
    }
    __syncthreads();
    for (int c = tid; c < 512; c += 256) {
        atomicAdd(&g_sums[c], ss[c]);
        atomicAdd(&g_sums[512 + c], sq[c]);
    }
}

__global__ void rea_eqkv(const float* __restrict__ Q, const float* __restrict__ Kin,
                         const float* __restrict__ Vin) {
    int idx = blockIdx.x*blockDim.x + threadIdx.x;
    if (idx >= MM_*DD_/4) return;
    int c = (idx*4) & 511;
    float4 sm = *(const float4*)&g_sums[c];
    float4 sq = *(const float4*)&g_sums[512 + c];
    float4 hv = ((const float4*)g_hconv)[idx];
    float4 qv = ((const float4*)Q)[idx];
    float4 kv = ((const float4*)Kin)[idx];
    float4 vv = ((const float4*)Vin)[idx];
    float4 eq, ek, ev;
#define BN1(comp) { \
        float mu = sm.comp * (1.f/1568.f); \
        float var = sq.comp * (1.f/1568.f) - mu*mu; \
        float xn = fmaxf((hv.comp - mu) * rsqrtf(var + EPSV_), 0.f); \
        eq.comp = to_tf32(xn + qv.comp); \
        ek.comp = to_tf32(xn + kv.comp); \
        ev.comp = to_tf32(xn + vv.comp); }
    BN1(x) BN1(y) BN1(z) BN1(w)
#undef BN1
    ((float4*)g_eq)[idx] = eq;
    ((float4*)g_ek)[idx] = ek;
    ((float4*)g_ev)[idx] = ev;
}

// ---------------- per-pair gate: one pair per LANE, j-dim tiled in smem ------
#define PTILE 64
__global__ void __launch_bounds__(512)
rea_pair(const float* __restrict__ Wc2, const float* __restrict__ bc1,
         const float* __restrict__ gc, const float* __restrict__ bcln,
         const float* __restrict__ bc2, const float* __restrict__ br1,
         const float* __restrict__ gr, const float* __restrict__ brln) {
    __shared__ float ck_s[PTILE*49];
    __shared__ float pq_s[PTILE*49];
    __shared__ float wct_s[PTILE*16];
    __shared__ float2 ab_s[PTILE];
    __shared__ float w2_s[PTILE];
    __shared__ float s_bc2[16], s_reg[16];

    int b = blockIdx.x;
    int t = threadIdx.x;
    int p = blockIdx.y*512 + t;
    int q = p / 49, k = p - q*49;
    bool act = q < 49;
    int qc = act ? q : 48;
    int b49 = b*49;

    if (t < NRELV_) { s_bc2[t] = bc2[t]; s_reg[t] = g_reg[t]; }
    if (t < PTILE) { wct_s[t*16 + 14] = 0.f; wct_s[t*16 + 15] = 0.f; }

    // ======== channel branch (256 dims, offset 512) ========
    float s1 = 0.f, s2 = 0.f;
    for (int jt = 0; jt < 4; jt++) {
        int j0 = jt*PTILE;
        __syncthreads();
        for (int idx = t; idx < PTILE*49; idx += 512) {
            int kk = idx >> 6, j = idx & 63;
            size_t base = (size_t)(b49 + kk)*1280 + 512 + j0 + j;
            ck_s[j*49 + kk] = g_ekcat[base];
            pq_s[j*49 + kk] = g_eqcat[base] + bc1[j0 + j];
        }
        __syncthreads();
#pragma unroll 8
        for (int j = 0; j < PTILE; j++) {
            float xc = pq_s[j*49 + qc] + ck_s[j*49 + k];
            s1 += xc; s2 = fmaf(xc, xc, s2);
        }
    }
    float mu = s1 * (1.f/256.f);
    float rs = rsqrtf(s2*(1.f/256.f) - mu*mu + EPSV_);

    float lg[14];
#pragma unroll
    for (int i = 0; i < 14; i++) lg[i] = 0.f;
    for (int jt = 0; jt < 4; jt++) {
        int j0 = jt*PTILE;
        __syncthreads();
        for (int idx = t; idx < PTILE*49; idx += 512) {
            int kk = idx >> 6, j = idx & 63;
            size_t base = (size_t)(b49 + kk)*1280 + 512 + j0 + j;
            ck_s[j*49 + kk] = g_ekcat[base];
            pq_s[j*49 + kk] = g_eqcat[base] + bc1[j0 + j];
        }
        for (int idx = t; idx < PTILE*14; idx += 512) {
            int j = idx / 14, tt = idx - j*14;
            wct_s[j*16 + tt] = Wc2[(size_t)(j0 + j)*14 + tt];
        }
        if (t < PTILE) ab_s[t] = make_float2(gc[j0 + t], bcln[j0 + t]);
        __syncthreads();
#pragma unroll 4
        for (int j = 0; j < PTILE; j++) {
            float xc = pq_s[j*49 + qc] + ck_s[j*49 + k];
            float2 ab = ab_s[j];
            float A = rs * ab.x;
            float y = fmaxf(fmaf(xc, A, ab.y - mu*A), 0.f);
            const float4* w4 = (const float4*)&wct_s[j*16];
            float4 w0 = w4[0], w1 = w4[1], w2v = w4[2], w3v = w4[3];
            lg[0]  = fmaf(y, w0.x,  lg[0]);  lg[1]  = fmaf(y, w0.y,  lg[1]);
            lg[2]  = fmaf(y, w0.z,  lg[2]);  lg[3]  = fmaf(y, w0.w,  lg[3]);
            lg[4]  = fmaf(y, w1.x,  lg[4]);  lg[5]  = fmaf(y, w1.y,  lg[5]);
            lg[6]  = fmaf(y, w1.z,  lg[6]);  lg[7]  = fmaf(y, w1.w,  lg[7]);
            lg[8]  = fmaf(y, w2v.x, lg[8]);  lg[9]  = fmaf(y, w2v.y, lg[9]);
            lg[10] = fmaf(y, w2v.z, lg[10]); lg[11] = fmaf(y, w2v.w, lg[11]);
            lg[12] = fmaf(y, w3v.x, lg[12]); lg[13] = fmaf(y, w3v.y, lg[13]);
        }
    }
    float mx = -1e30f;
#pragma unroll
    for (int tt = 0; tt < 14; tt++) { lg[tt] += s_bc2[tt]; mx = fmaxf(mx, lg[tt]); }
    float se = 0.f, dg = 0.f;
#pragma unroll
    for (int tt = 0; tt < 14; tt++) { float e = expf(lg[tt] - mx); se += e; dg += e*s_reg[tt]; }
    float proj = dg / se * (1.f/(1.f + 1e-8f));

    // ======== relation branch (512 dims, offset 768) ========
    s1 = 0.f; s2 = 0.f;
    for (int jt = 0; jt < 8; jt++) {
        int j0 = jt*PTILE;
        __syncthreads();
        for (int idx = t; idx < PTILE*49; idx += 512) {
            int kk = idx >> 6, j = idx & 63;
            size_t base = (size_t)(b49 + kk)*1280 + 768 + j0 + j;
            ck_s[j*49 + kk] = g_ekcat[base];
            pq_s[j*49 + kk] = g_eqcat[base] + br1[j0 + j];
        }
        __syncthreads();
#pragma unroll 8
        for (int j = 0; j < PTILE; j++) {
            float xr = pq_s[j*49 + qc] + ck_s[j*49 + k];
            s1 += xr; s2 = fmaf(xr, xr, s2);
        }
    }
    float mur = s1 * (1.f/512.f);
    float rsr = rsqrtf(s2*(1.f/512.f) - mur*mur + EPSV_);

    float dr = 0.f;
    for (int jt = 0; jt < 8; jt++) {
        int j0 = jt*PTILE;
        __syncthreads();
        for (int idx = t; idx < PTILE*49; idx += 512) {
            int kk = idx >> 6, j = idx & 63;
            size_t base = (size_t)(b49 + kk)*1280 + 768 + j0 + j;
            ck_s[j*49 + kk] = g_ekcat[base];
            pq_s[j*49 + kk] = g_eqcat[base] + br1[j0 + j];
        }
        if (t < PTILE) {
            ab_s[t] = make_float2(gr[j0 + t], brln[j0 + t]);
            w2_s[t] = g_wr2g[j0 + t];
        }
        __syncthreads();
#pragma unroll 8
        for (int j = 0; j < PTILE; j++) {
            float xr = pq_s[j*49 + qc] + ck_s[j*49 + k];
            float2 ab = ab_s[j];
            float A = rsr * ab.x;
            float y = fmaxf(fmaf(xr, A, ab.y - mur*A), 0.f);
            dr = fmaf(y, w2_s[j], dr);
        }
    }

    if (act) {
        float ga = dr + proj + g_c0[0];
        g_gate[(size_t)(b49 + q)*49 + k] = 1.f/(1.f + expf(-ga));
    }
}

// ---------------- attention per (b,h); also zeroes d_out for atomic gout ----
__global__ void __launch_bounds__(256)
rea_attn(float* __restrict__ out, float* __restrict__ dz) {
    __shared__ float Qt[49*65], Kt[49*65], Vt[49*65];
    __shared__ float wrow[8][52];
    int h = blockIdx.x, b = blockIdx.y;
    int t = threadIdx.x, w = t >> 5, l = t & 31;

    {
        float4 z4 = make_float4(0.f, 0.f, 0.f, 0.f);
        float4* dst = (float4*)dz + (size_t)(b*8 + h)*784;
        for (int i = t; i < 784; i += 256) dst[i] = z4;
    }

    for (int idx = t; idx < 49*64; idx += 256) {
        int q = idx >> 6, d = idx & 63;
        Qt[q*65 + d] = g_eqcat[(size_t)(b*49 + q)*1280 + h*64 + d];
        Kt[q*65 + d] = g_ekcat[(size_t)(b*49 + q)*1280 + h*64 + d];
        Vt[q*65 + d] = g_v[(size_t)(b*49 + q)*512 + h*64 + d];
    }
    __syncthreads();

    for (int q = w; q < 49; q += 8) {
        int m = b*49 + q;
        int k2 = l + 32;
        bool v2 = k2 < 49;
        float g1 = g_gate[(size_t)m*49 + l];
        float g2 = v2 ? g_gate[(size_t)m*49 + k2] : 0.f;
        const float* qr  = Qt + q*65;
        const float* k1r = Kt + l*65;
        const float* k2r = Kt + (v2 ? k2 : l)*65;
        float d1 = 0.f, d2 = 0.f;
#pragma unroll 8
        for (int d = 0; d < 64; d++) {
            float qv = qr[d];
            d1 += qv * k1r[d];
            d2 += qv * k2r[d];
        }
        float lv1 = d1*SCALEV_*(1.f + g1);
        float lv2 = v2 ? d2*SCALEV_*(1.f + g2) : -1e30f;
        float mx = fmaxf(lv1, lv2);
#pragma unroll
        for (int o = 16; o > 0; o >>= 1) mx = fmaxf(mx, __shfl_xor_sync(0xffffffffu, mx, o));
        float e1 = expf(lv1 - mx);
        float e2 = v2 ? expf(lv2 - mx) : 0.f;
        float ssum = wsum(e1 + e2);
        float inv = 1.f / ssum;
        wrow[w][l] = e1 * inv;
        if (v2) wrow[w][k2] = e2 * inv;
        __syncwarp();
        float a1 = 0.f, a2 = 0.f;
        for (int k = 0; k < 49; k++) {
            float wk = wrow[w][k];
            a1 += wk * Vt[k*65 + l];
            a2 += wk * Vt[k*65 + l + 32];
        }
        out[(size_t)m*512 + h*64 + l]      = to_tf32(a1);
        out[(size_t)m*512 + h*64 + l + 32] = to_tf32(a2);
        __syncwarp();
    }
}

// ---------------- launch ----------------
extern "C" void kernel_launch(void* const* d_in, const int* in_sizes, int n_in,
                              void* d_out, int out_size) {
    const float* Q     = (const float*)d_in[0];
    const float* Kin   = (const float*)d_in[1];
    const float* Vin   = (const float*)d_in[2];
    const float* Wq    = (const float*)d_in[3];
    const float* bq    = (const float*)d_in[4];
    const float* Wk    = (const float*)d_in[5];
    const float* bk    = (const float*)d_in[6];
    const float* Wv    = (const float*)d_in[7];
    const float* bv    = (const float*)d_in[8];
    const float* Wo    = (const float*)d_in[9];
    const float* bo    = (const float*)d_in[10];
    const float* rel   = (const float*)d_in[11];
    const float* Wproj = (const float*)d_in[12];
    const float* bproj = (const float*)d_in[13];
    const float* Wgate = (const float*)d_in[14];
    const float* bgate = (const float*)d_in[15];
    const float* Wc1   = (const float*)d_in[16];
    const float* bc1   = (const float*)d_in[17];
    const float* gc    = (const float*)d_in[18];
    const float* bcln  = (const float*)d_in[19];
    const float* Wc2   = (const float*)d_in[20];
    const float* bc2   = (const float*)d_in[21];
    const float* Wr1   = (const float*)d_in[22];
    const float* br1   = (const float*)d_in[23];
    const float* gr    = (const float*)d_in[24];
    const float* brln  = (const float*)d_in[25];
    const float* Wr2   = (const float*)d_in[26];
    const float* br2   = (const float*)d_in[27];
    const float* convW = (const float*)d_in[28];
    const float* convb = (const float*)d_in[29];

    void *p_hconv, *p_qr, *p_att, *p_convWt, *p_Wor;
    cudaGetSymbolAddress(&p_hconv, g_hconv);
    cudaGetSymbolAddress(&p_qr, g_qr);
    cudaGetSymbolAddress(&p_att, g_att);
    cudaGetSymbolAddress(&p_convWt, g_convWt);
    cudaGetSymbolAddress(&p_Wor, g_Wor);

    static bool attr_set = false;
    if (!attr_set) {
        cudaFuncSetAttribute(rea_gconv, cudaFuncAttributeMaxDynamicSharedMemorySize, GEMM_SMEM);
        cudaFuncSetAttribute(rea_gqkv, cudaFuncAttributeMaxDynamicSharedMemorySize, GEMM_SMEM);
        cudaFuncSetAttribute(rea_gout, cudaFuncAttributeMaxDynamicSharedMemorySize, GEMM_SMEM);
        attr_set = true;
    }

    // gconv stays 4th launch (ncu captures launch idx 3)
    rea_pre<<<256 + (MM_*DD_/4 + 255)/256, 256>>>(convW, Q);
    rea_k0<<<65, 256>>>(Wr2, Wproj, Wgate, rel, br2, bproj, bgate);
    rea_repack_bcat<<<(512*1280 + 255)/256, 256>>>(Wq, Wk, Wc1, Wr1, bq, bk, Wv, Wo);
    rea_gconv<<<dim3(4, 13, 9), 128, GEMM_SMEM>>>((const float*)p_qr, (const float*)p_convWt,
                                                  convb, (float*)p_hconv);

    rea_bn_stats<<<49, 256>>>();
    rea_eqkv<<<(MM_*DD_/4 + 255)/256, 256>>>(Q, Kin, Vin);

    rea_gqkv<<<312, 128, GEMM_SMEM>>>(bv);

    rea_pair<<<dim3(32, 5), 512>>>(Wc2, bc1, gc, bcln, bc2, br1, gr, brln);
    rea_attn<<<dim3(8, 32), 256>>>((float*)p_att, (float*)d_out);

    rea_gout<<<dim3(4, 13, 4), 128, GEMM_SMEM>>>((const float*)p_att, (const float*)p_Wor,
                                                 bo, (float*)d_out);
}

// round 9
// speedup vs baseline: 1.7151x; 1.0826x over previous
#include <cuda_runtime.h>
#include <math.h>
#include <stdint.h>

// Problem constants
#define BB_ 32
#define NN_ 49
#define DD_ 512
#define MM_ (BB_*NN_)      // 1568
#define NRELV_ 14
#define EPSV_ 1e-5f
#define SCALEV_ 0.125f     // 1/sqrt(64)

// ---------------- device scratch (no allocations allowed) ----------------
__device__ __align__(256) float g_hconv[MM_*DD_];
__device__ __align__(256) float g_hpart[9*MM_*DD_];   // split-K partials (no atomics)
__device__ __align__(256) float g_qr[MM_*DD_];
__device__ __align__(256) float g_eq[MM_*DD_];
__device__ __align__(256) float g_ek[MM_*DD_];
__device__ __align__(256) float g_ev[MM_*DD_];
__device__ __align__(256) float g_eqcat[MM_*1280];
__device__ __align__(256) float g_ekcat[MM_*1280];
__device__ __align__(256) float g_v[MM_*DD_];
__device__ __align__(256) float g_att[MM_*DD_];
__device__ __align__(256) float g_convWt[9*512*512];
__device__ __align__(256) float g_Bq[512*1280];
__device__ __align__(256) float g_Bk[512*1280];
__device__ __align__(256) float g_Wvr[512*512];
__device__ __align__(256) float g_Wor[512*512];
__device__ __align__(256) float g_biasq[1280];
__device__ __align__(256) float g_biask[1280];
__device__ float g_sums[1024];
__device__ float g_wr2g[512];
__device__ float g_reg[NRELV_];
__device__ float g_c0[1];
__device__ float g_gate[MM_*NN_];

__device__ __forceinline__ float wsum(float v) {
#pragma unroll
    for (int o = 16; o > 0; o >>= 1) v += __shfl_xor_sync(0xffffffffu, v, o);
    return v;
}

__device__ __forceinline__ float to_tf32(float x) {
    uint32_t u;
    asm("cvt.rna.tf32.f32 %0, %1;" : "=r"(u) : "f"(x));
    return __uint_as_float(u);
}

__device__ __forceinline__ void mma_tf32(float* c,
                                         uint32_t a0, uint32_t a1, uint32_t a2, uint32_t a3,
                                         uint32_t b0, uint32_t b1) {
    asm volatile("mma.sync.aligned.m16n8k8.row.col.f32.tf32.tf32.f32 "
                 "{%0,%1,%2,%3}, {%4,%5,%6,%7}, {%8,%9}, {%0,%1,%2,%3};"
                 : "+f"(c[0]), "+f"(c[1]), "+f"(c[2]), "+f"(c[3])
                 : "r"(a0), "r"(a1), "r"(a2), "r"(a3), "r"(b0), "r"(b1));
}

__device__ __forceinline__ void cp16(uint32_t dst, const float* src, bool pred) {
    int sz = pred ? 16 : 0;
    asm volatile("cp.async.cg.shared.global [%0], [%1], 16, %2;\n"
                 :: "r"(dst), "l"(src), "r"(sz));
}
#define CP_COMMIT() asm volatile("cp.async.commit_group;" ::: "memory")
#define CP_WAIT1()  asm volatile("cp.async.wait_group 1;" ::: "memory")

// ---------------- fused prologue: conv repack + Q round + k0 + bcat ----------
// grid layout by blockIdx.x:
//   [0,256)      conv weight repack (32o x 32c tiles)
//   [256,1040)   Q tf32 round (float4), block 256 also zeroes g_sums
//   [1040,1105)  k0 folded gate vectors (65 blocks)
//   [1105,3665)  bcat repack + Wv/Wo round + biases (2560 blocks)
__global__ void __launch_bounds__(256)
rea_prologue(const float* __restrict__ convW, const float* __restrict__ Q,
             const float* __restrict__ Wr2, const float* __restrict__ Wproj,
             const float* __restrict__ Wg, const float* __restrict__ rel,
             const float* __restrict__ br2, const float* __restrict__ bproj,
             const float* __restrict__ bgate,
             const float* __restrict__ Wq, const float* __restrict__ Wk,
             const float* __restrict__ Wc1, const float* __restrict__ Wr1,
             const float* __restrict__ bq, const float* __restrict__ bk,
             const float* __restrict__ Wv, const float* __restrict__ Wo) {
    int bx = blockIdx.x, t = threadIdx.x;
    if (bx < 256) {
        __shared__ float ts[32*289];
        int o0 = (bx & 15)*32, c0 = (bx >> 4)*32;
        for (int idx = t; idx < 32*288; idx += 256) {
            int o = idx / 288, r = idx - o*288;   // r = c_local*9 + tap
            ts[o*289 + r] = to_tf32(convW[((size_t)(o0 + o)*512 + c0)*9 + r]);
        }
        __syncthreads();
        for (int idx = t; idx < 288*32; idx += 256) {
            int row = idx >> 5, o = idx & 31;
            int c = row / 9, tap = row - c*9;
            g_convWt[(size_t)tap*262144 + (size_t)(c0 + c)*512 + o0 + o] = ts[o*289 + row];
        }
    } else if (bx < 1040) {
        int idx = (bx - 256)*256 + t;
        if (idx < MM_*DD_/4) {
            float4 qv = ((const float4*)Q)[idx];
            float4 r;
            r.x = to_tf32(qv.x); r.y = to_tf32(qv.y);
            r.z = to_tf32(qv.z); r.w = to_tf32(qv.w);
            ((float4*)g_qr)[idx] = r;
        }
        if (bx == 256)
            ((float4*)g_sums)[t] = make_float4(0.f, 0.f, 0.f, 0.f);
    } else if (bx < 1105) {
        __shared__ float wg_s[512];
        __shared__ float wpg_s[64];
        int kb = bx - 1040;
        wg_s[t] = Wg[t];
        wg_s[t + 256] = Wg[t + 256];
        __syncthreads();
        int w = t >> 5, l = t & 31;
        if (kb < 64) {
            int row = kb*8 + w;
            float s = 0.f;
            for (int j = l; j < 512; j += 32) s += Wr2[(size_t)row*512 + j] * wg_s[j];
            s = wsum(s);
            if (l == 0) g_wr2g[row] = s;
        } else {
            for (int r = w; r < 64; r += 8) {
                float s = 0.f;
                for (int j = l; j < 512; j += 32) s += Wproj[(size_t)r*512 + j] * wg_s[j];
                s = wsum(s);
                if (l == 0) wpg_s[r] = s;
            }
            __syncthreads();
            if (t < NRELV_) {
                float s = 0.f;
                for (int d = 0; d < 64; d++) s += rel[t*64 + d] * wpg_s[d];
                g_reg[t] = s;
            }
            if (w == 7) {
                float s = 0.f;
                for (int j = l; j < 512; j += 32) s += (br2[j] + bproj[j]) * wg_s[j];
                s = wsum(s);
                if (l == 0) g_c0[0] = s + bgate[0];
            }
        }
    } else {
        int idx = (bx - 1105)*256 + t;
        if (idx < 512*1280) {
            int k = idx / 1280, n = idx - k*1280;
            float vq, vk;
            if (n < 512)       { vq = Wq[(size_t)k*512 + n];              vk = Wk[(size_t)k*512 + n]; }
            else if (n < 768)  { vq = Wc1[(size_t)k*256 + (n-512)];       vk = Wc1[(size_t)(k+512)*256 + (n-512)]; }
            else               { vq = Wr1[(size_t)k*512 + (n-768)];       vk = Wr1[(size_t)(k+512)*512 + (n-768)]; }
            g_Bq[idx] = to_tf32(vq); g_Bk[idx] = to_tf32(vk);
        }
        if (idx < 512*512) {
            g_Wvr[idx] = to_tf32(Wv[idx]);
            g_Wor[idx] = to_tf32(Wo[idx]);
        }
        if (idx < 1280) {
            g_biasq[idx] = idx < 512 ? bq[idx] : 0.f;
            g_biask[idx] = idx < 512 ? bk[idx] : 0.f;
        }
    }
}

// ---------------- TF32 tensor-core GEMM core ----------------
// 128 threads = 4 warps (2M x 2N), warp tile 64x64, block tile 128x128, BK=32,
// 3-stage cp.async ring.
#define BMT 128
#define BNT 128
#define BKT 32
#define APAD 36
#define BPAD 136
#define SZA (BMT*APAD*4)
#define SZB (BKT*BPAD*4)
#define GEMM_SMEM (3*(BMT*APAD + BKT*BPAD)*4)

template <bool CONV, bool ATOMIC>
__device__ __forceinline__ void gemm_core(
    const float* __restrict__ A, const float* __restrict__ Bm,
    const float* __restrict__ bias, float* __restrict__ C,
    int M, int N, int lda, int kbase, int KT, int di, int dj,
    int m0, int n0, int zz,
    float* AsB, float* BsB) {

    int tid = threadIdx.x;
    int lane = tid & 31, warp = tid >> 5;
    int g = lane >> 2, t4 = lane & 3;
    int wm = (warp & 1) * 64, wn = (warp >> 1) * 64;

    uint32_t sA = (uint32_t)__cvta_generic_to_shared(AsB);
    uint32_t sB = (uint32_t)__cvta_generic_to_shared(BsB);

    float acc[4][8][4];
#pragma unroll
    for (int i = 0; i < 4; i++)
#pragma unroll
        for (int j = 0; j < 8; j++)
#pragma unroll
            for (int q = 0; q < 4; q++) acc[i][j][q] = 0.f;

    const float* aptr[8]; bool apred[8]; uint32_t adst[8];
    const float* bptr0; uint32_t bdst0;
#pragma unroll
    for (int h = 0; h < 8; h++) {
        int c = tid + h*128;
        int m = c >> 3, kg = c & 7;
        int gm = m0 + m;
        bool pred;
        const float* p;
        if (!CONV) {
            pred = gm < M;
            p = A + (size_t)(pred ? gm : 0)*lda + kbase + kg*4;
        } else {
            int bb = gm / 49, pos = gm - bb*49;
            int pr = pos / 7, pc = pos - pr*7;
            int ii = pr + di, jj = pc + dj;
            pred = (gm < M) & ((unsigned)ii < 7u) & ((unsigned)jj < 7u);
            p = pred ? (A + ((size_t)(bb*49 + ii*7 + jj))*512 + kg*4) : A;
        }
        apred[h] = pred; aptr[h] = p;
        adst[h] = sA + (uint32_t)(m*APAD + kg*4)*4;
    }
    {
        int kr = tid >> 5, ng = tid & 31;
        bptr0 = Bm + (size_t)(kbase + kr)*N + n0 + ng*4;
        bdst0 = sB + (uint32_t)(kr*BPAD + ng*4)*4;
    }

    auto load_tile = [&](int kt, int buf) {
#pragma unroll
        for (int h = 0; h < 8; h++)
            cp16(adst[h] + buf*SZA, aptr[h] + kt*BKT, apred[h]);
#pragma unroll
        for (int h = 0; h < 8; h++)
            cp16(bdst0 + buf*SZB + (uint32_t)h*4*BPAD*4,
                 bptr0 + (size_t)(kt*BKT + h*4)*N, true);
    };

    load_tile(0, 0); CP_COMMIT();
    if (KT > 1) load_tile(1, 1);
    CP_COMMIT();

    int buf = 0, nbuf = 2;
    for (int kt = 0; kt < KT; kt++) {
        CP_WAIT1();
        __syncthreads();
        if (kt + 2 < KT) load_tile(kt + 2, nbuf);
        CP_COMMIT();
        const float* as = AsB + buf*(BMT*APAD);
        const float* bs = BsB + buf*(BKT*BPAD);
#pragma unroll
        for (int k8 = 0; k8 < 4; k8++) {
            uint32_t af[4][4], bf[8][2];
#pragma unroll
            for (int i = 0; i < 4; i++) {
                int mrow = wm + i*16 + g;
                af[i][0] = __float_as_uint(as[mrow*APAD + k8*8 + t4]);
                af[i][1] = __float_as_uint(as[(mrow + 8)*APAD + k8*8 + t4]);
                af[i][2] = __float_as_uint(as[mrow*APAD + k8*8 + t4 + 4]);
                af[i][3] = __float_as_uint(as[(mrow + 8)*APAD + k8*8 + t4 + 4]);
            }
#pragma unroll
            for (int j = 0; j < 8; j++) {
                int nc = wn + j*8 + g;
                bf[j][0] = __float_as_uint(bs[(k8*8 + t4)*BPAD + nc]);
                bf[j][1] = __float_as_uint(bs[(k8*8 + t4 + 4)*BPAD + nc]);
            }
#pragma unroll
            for (int i = 0; i < 4; i++)
#pragma unroll
                for (int j = 0; j < 8; j++)
                    mma_tf32(acc[i][j], af[i][0], af[i][1], af[i][2], af[i][3],
                             bf[j][0], bf[j][1]);
        }
        buf = (buf == 2) ? 0 : buf + 1;
        nbuf = (nbuf == 2) ? 0 : nbuf + 1;
    }

#pragma unroll
    for (int i = 0; i < 4; i++) {
        int mbase = m0 + wm + i*16 + g;
#pragma unroll
        for (int half = 0; half < 2; half++) {
            int gm = mbase + half*8;
            if (gm < M) {
#pragma unroll
                for (int j = 0; j < 8; j++) {
                    int gn = n0 + wn + j*8 + t4*2;
                    float v0 = acc[i][j][half*2 + 0];
                    float v1 = acc[i][j][half*2 + 1];
                    if (ATOMIC) {
                        if (zz == 0 && bias) { v0 += bias[gn]; v1 += bias[gn + 1]; }
                        atomicAdd(&C[(size_t)gm*N + gn],     v0);
                        atomicAdd(&C[(size_t)gm*N + gn + 1], v1);
                    } else {
                        if (bias) { v0 += bias[gn]; v1 += bias[gn + 1]; }
                        C[(size_t)gm*N + gn]     = v0;
                        C[(size_t)gm*N + gn + 1] = v1;
                    }
                }
            }
        }
    }
}

extern __shared__ float sm_gemm[];

// conv as implicit GEMM, split-K=9 (one tap per z), plain stores to partials
__global__ void __launch_bounds__(128, 2)
rea_gconv(const float* __restrict__ A, const float* __restrict__ Bm) {
    int tap = blockIdx.z;
    float* Cp = g_hpart + (size_t)tap*MM_*512;
    gemm_core<true, false>(A, Bm, nullptr, Cp, MM_, 512, 512,
                           tap*512, 16, tap/3 - 1, tap%3 - 1,
                           blockIdx.y*BMT, blockIdx.x*BNT, tap,
                           sm_gemm, sm_gemm + 3*BMT*APAD);
}

// batched eq/ek/ev projections, flat 312-block grid
__global__ void __launch_bounds__(128, 2)
rea_gqkv(const float* __restrict__ bv) {
    int bx = blockIdx.x;
    int z, lx;
    if (bx < 130)      { z = 0; lx = bx; }
    else if (bx < 260) { z = 1; lx = bx - 130; }
    else               { z = 2; lx = bx - 260; }
    int m0, n0;
    if (z < 2) { n0 = (lx % 10)*BNT; m0 = (lx / 10)*BMT; }
    else       { n0 = (lx & 3)*BNT;  m0 = (lx >> 2)*BMT; }
    const float* A    = z == 0 ? g_eq    : z == 1 ? g_ek    : g_ev;
    const float* Bm   = z == 0 ? g_Bq    : z == 1 ? g_Bk    : g_Wvr;
    const float* bias = z == 0 ? g_biasq : z == 1 ? g_biask : bv;
    float*       C    = z == 0 ? g_eqcat : z == 1 ? g_ekcat : g_v;
    int N = z < 2 ? 1280 : 512;
    gemm_core<false, false>(A, Bm, bias, C, MM_, N, 512, 0, 16, 0, 0,
                            m0, n0, 0, sm_gemm, sm_gemm + 3*BMT*APAD);
}

// output projection, split-K=4, atomic into pre-zeroed d_out
__global__ void __launch_bounds__(128, 2)
rea_gout(const float* __restrict__ A, const float* __restrict__ Bm,
         const float* __restrict__ bias, float* __restrict__ C) {
    gemm_core<false, true>(A, Bm, bias, C, MM_, 512, 512,
                           blockIdx.z*128, 4, 0, 0,
                           blockIdx.y*BMT, blockIdx.x*BNT, blockIdx.z,
                           sm_gemm, sm_gemm + 3*BMT*APAD);
}

// ---------------- reduce conv partials + bias -> hconv, BN stats -------------
// grid 98 x 256 threads; each thread owns one float4 column slice for 16 rows.
__global__ void __launch_bounds__(256)
rea_bn(const float* __restrict__ convb) {
    int t = threadIdx.x;
    int c4 = t & 127;
    int rh = t >> 7;
    int r0 = blockIdx.x*16;
    float4 cb = ((const float4*)convb)[c4];
    float4 s1 = make_float4(0.f, 0.f, 0.f, 0.f);
    float4 s2 = make_float4(0.f, 0.f, 0.f, 0.f);
#pragma unroll
    for (int it = 0; it < 8; it++) {
        int r = r0 + it*2 + rh;
        size_t off = (size_t)r*128 + c4;
        float4 a = cb;
#pragma unroll
        for (int tp = 0; tp < 9; tp++) {
            float4 p = ((const float4*)g_hpart)[(size_t)tp*(MM_*128) + off];
            a.x += p.x; a.y += p.y; a.z += p.z; a.w += p.w;
        }
        ((float4*)g_hconv)[off] = a;
        s1.x += a.x; s1.y += a.y; s1.z += a.z; s1.w += a.w;
        s2.x = fmaf(a.x, a.x, s2.x); s2.y = fmaf(a.y, a.y, s2.y);
        s2.z = fmaf(a.z, a.z, s2.z); s2.w = fmaf(a.w, a.w, s2.w);
    }
    int c = c4*4;
    atomicAdd(&g_sums[c + 0], s1.x); atomicAdd(&g_sums[c + 1], s1.y);
    atomicAdd(&g_sums[c + 2], s1.z); atomicAdd(&g_sums[c + 3], s1.w);
    atomicAdd(&g_sums[512 + c + 0], s2.x); atomicAdd(&g_sums[512 + c + 1], s2.y);
    atomicAdd(&g_sums[512 + c + 2], s2.z); atomicAdd(&g_sums[512 + c + 3], s2.w);
}

__global__ void rea_eqkv(const float* __restrict__ Q, const float* __restrict__ Kin,
                         const float* __restrict__ Vin) {
    int idx = blockIdx.x*blockDim.x + threadIdx.x;
    if (idx >= MM_*DD_/4) return;
    int c = (idx*4) & 511;
    float4 sm = *(const float4*)&g_sums[c];
    float4 sq = *(const float4*)&g_sums[512 + c];
    float4 hv = ((const float4*)g_hconv)[idx];
    float4 qv = ((const float4*)Q)[idx];
    float4 kv = ((const float4*)Kin)[idx];
    float4 vv = ((const float4*)Vin)[idx];
    float4 eq, ek, ev;
#define BN1(comp) { \
        float mu = sm.comp * (1.f/1568.f); \
        float var = sq.comp * (1.f/1568.f) - mu*mu; \
        float xn = fmaxf((hv.comp - mu) * rsqrtf(var + EPSV_), 0.f); \
        eq.comp = to_tf32(xn + qv.comp); \
        ek.comp = to_tf32(xn + kv.comp); \
        ev.comp = to_tf32(xn + vv.comp); }
    BN1(x) BN1(y) BN1(z) BN1(w)
#undef BN1
    ((float4*)g_eq)[idx] = eq;
    ((float4*)g_ek)[idx] = ek;
    ((float4*)g_ev)[idx] = ev;
}

// ---------------- per-pair gate: one pair per LANE, j-dim tiled in smem ------
#define PTILE 64
__global__ void __launch_bounds__(512)
rea_pair(const float* __restrict__ Wc2, const float* __restrict__ bc1,
         const float* __restrict__ gc, const float* __restrict__ bcln,
         const float* __restrict__ bc2, const float* __restrict__ br1,
         const float* __restrict__ gr, const float* __restrict__ brln) {
    __shared__ float ck_s[PTILE*49];
    __shared__ float pq_s[PTILE*49];
    __shared__ float wct_s[PTILE*16];
    __shared__ float2 ab_s[PTILE];
    __shared__ float w2_s[PTILE];
    __shared__ float s_bc2[16], s_reg[16];

    int b = blockIdx.x;
    int t = threadIdx.x;
    int p = blockIdx.y*512 + t;
    int q = p / 49, k = p - q*49;
    bool act = q < 49;
    int qc = act ? q : 48;
    int b49 = b*49;

    if (t < NRELV_) { s_bc2[t] = bc2[t]; s_reg[t] = g_reg[t]; }
    if (t < PTILE) { wct_s[t*16 + 14] = 0.f; wct_s[t*16 + 15] = 0.f; }

    // ======== channel branch (256 dims, offset 512) ========
    float s1 = 0.f, s2 = 0.f;
    for (int jt = 0; jt < 4; jt++) {
        int j0 = jt*PTILE;
        __syncthreads();
        for (int idx = t; idx < PTILE*49; idx += 512) {
            int kk = idx >> 6, j = idx & 63;
            size_t base = (size_t)(b49 + kk)*1280 + 512 + j0 + j;
            ck_s[j*49 + kk] = g_ekcat[base];
            pq_s[j*49 + kk] = g_eqcat[base] + bc1[j0 + j];
        }
        __syncthreads();
#pragma unroll 8
        for (int j = 0; j < PTILE; j++) {
            float xc = pq_s[j*49 + qc] + ck_s[j*49 + k];
            s1 += xc; s2 = fmaf(xc, xc, s2);
        }
    }
    float mu = s1 * (1.f/256.f);
    float rs = rsqrtf(s2*(1.f/256.f) - mu*mu + EPSV_);

    float lg[14];
#pragma unroll
    for (int i = 0; i < 14; i++) lg[i] = 0.f;
    for (int jt = 0; jt < 4; jt++) {
        int j0 = jt*PTILE;
        __syncthreads();
        for (int idx = t; idx < PTILE*49; idx += 512) {
            int kk = idx >> 6, j = idx & 63;
            size_t base = (size_t)(b49 + kk)*1280 + 512 + j0 + j;
            ck_s[j*49 + kk] = g_ekcat[base];
            pq_s[j*49 + kk] = g_eqcat[base] + bc1[j0 + j];
        }
        for (int idx = t; idx < PTILE*14; idx += 512) {
            int j = idx / 14, tt = idx - j*14;
            wct_s[j*16 + tt] = Wc2[(size_t)(j0 + j)*14 + tt];
        }
        if (t < PTILE) ab_s[t] = make_float2(gc[j0 + t], bcln[j0 + t]);
        __syncthreads();
#pragma unroll 4
        for (int j = 0; j < PTILE; j++) {
            float xc = pq_s[j*49 + qc] + ck_s[j*49 + k];
            float2 ab = ab_s[j];
            float A = rs * ab.x;
            float y = fmaxf(fmaf(xc, A, ab.y - mu*A), 0.f);
            const float4* w4 = (const float4*)&wct_s[j*16];
            float4 w0 = w4[0], w1 = w4[1], w2v = w4[2], w3v = w4[3];
            lg[0]  = fmaf(y, w0.x,  lg[0]);  lg[1]  = fmaf(y, w0.y,  lg[1]);
            lg[2]  = fmaf(y, w0.z,  lg[2]);  lg[3]  = fmaf(y, w0.w,  lg[3]);
            lg[4]  = fmaf(y, w1.x,  lg[4]);  lg[5]  = fmaf(y, w1.y,  lg[5]);
            lg[6]  = fmaf(y, w1.z,  lg[6]);  lg[7]  = fmaf(y, w1.w,  lg[7]);
            lg[8]  = fmaf(y, w2v.x, lg[8]);  lg[9]  = fmaf(y, w2v.y, lg[9]);
            lg[10] = fmaf(y, w2v.z, lg[10]); lg[11] = fmaf(y, w2v.w, lg[11]);
            lg[12] = fmaf(y, w3v.x, lg[12]); lg[13] = fmaf(y, w3v.y, lg[13]);
        }
    }
    float mx = -1e30f;
#pragma unroll
    for (int tt = 0; tt < 14; tt++) { lg[tt] += s_bc2[tt]; mx = fmaxf(mx, lg[tt]); }
    float se = 0.f, dg = 0.f;
#pragma unroll
    for (int tt = 0; tt < 14; tt++) { float e = expf(lg[tt] - mx); se += e; dg += e*s_reg[tt]; }
    float proj = dg / se * (1.f/(1.f + 1e-8f));

    // ======== relation branch (512 dims, offset 768) ========
    s1 = 0.f; s2 = 0.f;
    for (int jt = 0; jt < 8; jt++) {
        int j0 = jt*PTILE;
        __syncthreads();
        for (int idx = t; idx < PTILE*49; idx += 512) {
            int kk = idx >> 6, j = idx & 63;
            size_t base = (size_t)(b49 + kk)*1280 + 768 + j0 + j;
            ck_s[j*49 + kk] = g_ekcat[base];
            pq_s[j*49 + kk] = g_eqcat[base] + br1[j0 + j];
        }
        __syncthreads();
#pragma unroll 8
        for (int j = 0; j < PTILE; j++) {
            float xr = pq_s[j*49 + qc] + ck_s[j*49 + k];
            s1 += xr; s2 = fmaf(xr, xr, s2);
        }
    }
    float mur = s1 * (1.f/512.f);
    float rsr = rsqrtf(s2*(1.f/512.f) - mur*mur + EPSV_);

    float dr = 0.f;
    for (int jt = 0; jt < 8; jt++) {
        int j0 = jt*PTILE;
        __syncthreads();
        for (int idx = t; idx < PTILE*49; idx += 512) {
            int kk = idx >> 6, j = idx & 63;
            size_t base = (size_t)(b49 + kk)*1280 + 768 + j0 + j;
            ck_s[j*49 + kk] = g_ekcat[base];
            pq_s[j*49 + kk] = g_eqcat[base] + br1[j0 + j];
        }
        if (t < PTILE) {
            ab_s[t] = make_float2(gr[j0 + t], brln[j0 + t]);
            w2_s[t] = g_wr2g[j0 + t];
        }
        __syncthreads();
#pragma unroll 8
        for (int j = 0; j < PTILE; j++) {
            float xr = pq_s[j*49 + qc] + ck_s[j*49 + k];
            float2 ab = ab_s[j];
            float A = rsr * ab.x;
            float y = fmaxf(fmaf(xr, A, ab.y - mur*A), 0.f);
            dr = fmaf(y, w2_s[j], dr);
        }
    }

    if (act) {
        float ga = dr + proj + g_c0[0];
        g_gate[(size_t)(b49 + q)*49 + k] = 1.f/(1.f + expf(-ga));
    }
}

// ---------------- attention per (b,h); also zeroes d_out for atomic gout ----
__global__ void __launch_bounds__(256)
rea_attn(float* __restrict__ out, float* __restrict__ dz) {
    __shared__ float Qt[49*65], Kt[49*65], Vt[49*65];
    __shared__ float wrow[8][52];
    int h = blockIdx.x, b = blockIdx.y;
    int t = threadIdx.x, w = t >> 5, l = t & 31;

    {
        float4 z4 = make_float4(0.f, 0.f, 0.f, 0.f);
        float4* dst = (float4*)dz + (size_t)(b*8 + h)*784;
        for (int i = t; i < 784; i += 256) dst[i] = z4;
    }

    for (int idx = t; idx < 49*64; idx += 256) {
        int q = idx >> 6, d = idx & 63;
        Qt[q*65 + d] = g_eqcat[(size_t)(b*49 + q)*1280 + h*64 + d];
        Kt[q*65 + d] = g_ekcat[(size_t)(b*49 + q)*1280 + h*64 + d];
        Vt[q*65 + d] = g_v[(size_t)(b*49 + q)*512 + h*64 + d];
    }
    __syncthreads();

    for (int q = w; q < 49; q += 8) {
        int m = b*49 + q;
        int k2 = l + 32;
        bool v2 = k2 < 49;
        float g1 = g_gate[(size_t)m*49 + l];
        float g2 = v2 ? g_gate[(size_t)m*49 + k2] : 0.f;
        const float* qr  = Qt + q*65;
        const float* k1r = Kt + l*65;
        const float* k2r = Kt + (v2 ? k2 : l)*65;
        float d1 = 0.f, d2 = 0.f;
#pragma unroll 8
        for (int d = 0; d < 64; d++) {
            float qv = qr[d];
            d1 += qv * k1r[d];
            d2 += qv * k2r[d];
        }
        float lv1 = d1*SCALEV_*(1.f + g1);
        float lv2 = v2 ? d2*SCALEV_*(1.f + g2) : -1e30f;
        float mx = fmaxf(lv1, lv2);
#pragma unroll
        for (int o = 16; o > 0; o >>= 1) mx = fmaxf(mx, __shfl_xor_sync(0xffffffffu, mx, o));
        float e1 = expf(lv1 - mx);
        float e2 = v2 ? expf(lv2 - mx) : 0.f;
        float ssum = wsum(e1 + e2);
        float inv = 1.f / ssum;
        wrow[w][l] = e1 * inv;
        if (v2) wrow[w][k2] = e2 * inv;
        __syncwarp();
        float a1 = 0.f, a2 = 0.f;
        for (int k = 0; k < 49; k++) {
            float wk = wrow[w][k];
            a1 += wk * Vt[k*65 + l];
            a2 += wk * Vt[k*65 + l + 32];
        }
        out[(size_t)m*512 + h*64 + l]      = to_tf32(a1);
        out[(size_t)m*512 + h*64 + l + 32] = to_tf32(a2);
        __syncwarp();
    }
}

// ---------------- launch ----------------
extern "C" void kernel_launch(void* const* d_in, const int* in_sizes, int n_in,
                              void* d_out, int out_size) {
    const float* Q     = (const float*)d_in[0];
    const float* Kin   = (const float*)d_in[1];
    const float* Vin   = (const float*)d_in[2];
    const float* Wq    = (const float*)d_in[3];
    const float* bq    = (const float*)d_in[4];
    const float* Wk    = (const float*)d_in[5];
    const float* bk    = (const float*)d_in[6];
    const float* Wv    = (const float*)d_in[7];
    const float* bv    = (const float*)d_in[8];
    const float* Wo    = (const float*)d_in[9];
    const float* bo    = (const float*)d_in[10];
    const float* rel   = (const float*)d_in[11];
    const float* Wproj = (const float*)d_in[12];
    const float* bproj = (const float*)d_in[13];
    const float* Wgate = (const float*)d_in[14];
    const float* bgate = (const float*)d_in[15];
    const float* Wc1   = (const float*)d_in[16];
    const float* bc1   = (const float*)d_in[17];
    const float* gc    = (const float*)d_in[18];
    const float* bcln  = (const float*)d_in[19];
    const float* Wc2   = (const float*)d_in[20];
    const float* bc2   = (const float*)d_in[21];
    const float* Wr1   = (const float*)d_in[22];
    const float* br1   = (const float*)d_in[23];
    const float* gr    = (const float*)d_in[24];
    const float* brln  = (const float*)d_in[25];
    const float* Wr2   = (const float*)d_in[26];
    const float* br2   = (const float*)d_in[27];
    const float* convW = (const float*)d_in[28];
    const float* convb = (const float*)d_in[29];

    void *p_qr, *p_att, *p_convWt, *p_Wor;
    cudaGetSymbolAddress(&p_qr, g_qr);
    cudaGetSymbolAddress(&p_att, g_att);
    cudaGetSymbolAddress(&p_convWt, g_convWt);
    cudaGetSymbolAddress(&p_Wor, g_Wor);

    static bool attr_set = false;
    if (!attr_set) {
        cudaFuncSetAttribute(rea_gconv, cudaFuncAttributeMaxDynamicSharedMemorySize, GEMM_SMEM);
        cudaFuncSetAttribute(rea_gqkv, cudaFuncAttributeMaxDynamicSharedMemorySize, GEMM_SMEM);
        cudaFuncSetAttribute(rea_gout, cudaFuncAttributeMaxDynamicSharedMemorySize, GEMM_SMEM);
        attr_set = true;
    }

    // 8 launches; ncu captures launch idx 3 => rea_eqkv this round
    rea_prologue<<<3665, 256>>>(convW, Q, Wr2, Wproj, Wgate, rel, br2, bproj, bgate,
                                Wq, Wk, Wc1, Wr1, bq, bk, Wv, Wo);
    rea_gconv<<<dim3(4, 13, 9), 128, GEMM_SMEM>>>((const float*)p_qr,
                                                  (const float*)p_convWt);
    rea_bn<<<98, 256>>>(convb);
    rea_eqkv<<<(MM_*DD_/4 + 255)/256, 256>>>(Q, Kin, Vin);

    rea_gqkv<<<312, 128, GEMM_SMEM>>>(bv);

    rea_pair<<<dim3(32, 5), 512>>>(Wc2, bc1, gc, bcln, bc2, br1, gr, brln);
    rea_attn<<<dim3(8, 32), 256>>>((float*)p_att, (float*)d_out);

    rea_gout<<<dim3(4, 13, 4), 128, GEMM_SMEM>>>((const float*)p_att, (const float*)p_Wor,
                                                 bo, (float*)d_out);
}